// round 8
// baseline (speedup 1.0000x reference)
#include <cuda_runtime.h>
#include <math.h>
#include <stdint.h>

// Tree-LSTM, 4-ary, depth 8. E=H=128, A=4. N_NODES=87381, leaves=65536.
// R8: leaf level fully fused — HMMA tf32 GEMM with gate-interleaved weight layout
// (col = h*4+gate), epilogue through smem, writes h/c directly. No g_Y for leaves.
// Inner levels unchanged (HMMA -> g_Y -> elem kernel).

#define NN     87381
#define NLEAF  65536

// ---------------- scratch ----------------
__device__ float g_Y[(size_t)16384 * 896];   // inner-level GEMM output only
__device__ float g_M[896 * 640];             // inner combined weight (tf32-rounded)
__device__ float g_bias[896];
__device__ float g_Mleaf[512 * 128];         // leaf weight, PERMUTED col = h*4+gate
__device__ float g_bleaf[512];               // leaf bias, PERMUTED (iou consts + b_wf)
__device__ float g_cuf[512];                 // leaf f-gate const U_f@h0+b_uf (a*128+h)

__device__ __forceinline__ float sigf(float x) { return 1.0f / (1.0f + expf(-x)); }
__device__ __forceinline__ uint32_t f2tf(float f) {
    uint32_t r; asm("cvt.rna.tf32.f32 %0, %1;" : "=r"(r) : "f"(f)); return r;
}

// ---------------- prep ----------------
__global__ void prep_M_kernel(const float* __restrict__ W_iou, const float* __restrict__ U_iou,
                              const float* __restrict__ b_iou, const float* __restrict__ b_uiou,
                              const float* __restrict__ W_f,  const float* __restrict__ U_f,
                              const float* __restrict__ b_wf, const float* __restrict__ b_uf) {
    int stride = gridDim.x * blockDim.x;
    int idx = blockIdx.x * blockDim.x + threadIdx.x;
    for (int t = idx; t < 896 * 640; t += stride) {
        int c = t / 640, k = t - c * 640;
        float v;
        if (c < 384) v = (k < 128) ? W_iou[c * 128 + k] : U_iou[c * 512 + (k - 128)];
        else {
            int cc = c - 384;
            v = (k < 128) ? W_f[(cc & 127) * 128 + k] : U_f[cc * 512 + (k - 128)];
        }
        g_M[t] = __uint_as_float(f2tf(v));
    }
    // leaf weight, permuted: col c = h*4+g ; g<3 -> W_iou[g*128+h], g=3 -> W_f[h]
    for (int t = idx; t < 512 * 128; t += stride) {
        int c = t >> 7, k = t & 127;
        int h = c >> 2, g = c & 3;
        float v = (g < 3) ? W_iou[(g * 128 + h) * 128 + k] : W_f[h * 128 + k];
        g_Mleaf[t] = __uint_as_float(f2tf(v));
    }
    if (idx < 896)
        g_bias[idx] = (idx < 384) ? (b_iou[idx] + b_uiou[idx])
                                  : (b_wf[(idx - 384) & 127] + b_uf[idx - 384]);
}

__global__ void prep_const_kernel(const float* __restrict__ U_iou, const float* __restrict__ b_iou,
                                  const float* __restrict__ b_uiou, const float* __restrict__ U_f,
                                  const float* __restrict__ b_uf, const float* __restrict__ h0,
                                  const float* __restrict__ b_wf) {
    int c = blockIdx.x * blockDim.x + threadIdx.x;
    if (c < 384) {
        int g = c >> 7, h = c & 127;
        float s = b_iou[c] + b_uiou[c];
        for (int k = 0; k < 512; k++) s += U_iou[c * 512 + k] * h0[k];
        g_bleaf[h * 4 + g] = s;                     // permuted
    } else if (c < 896) {
        int cc = c - 384;
        float s = b_uf[cc];
        for (int k = 0; k < 512; k++) s += U_f[cc * 512 + k] * h0[k];
        g_cuf[cc] = s;
        if (cc < 128) g_bleaf[cc * 4 + 3] = b_wf[cc];   // permuted
    }
}

// ---------------- mma helper ----------------
__device__ __forceinline__ void mma_tf32(float* c, const uint32_t* a, const uint32_t* b) {
    asm volatile(
        "mma.sync.aligned.m16n8k8.row.col.f32.tf32.tf32.f32 "
        "{%0,%1,%2,%3}, {%4,%5,%6,%7}, {%8,%9}, {%0,%1,%2,%3};"
        : "+f"(c[0]), "+f"(c[1]), "+f"(c[2]), "+f"(c[3])
        : "r"(a[0]), "r"(a[1]), "r"(a[2]), "r"(a[3]), "r"(b[0]), "r"(b[1]));
}

// ---------------- fused leaf: HMMA GEMM (128x128 tile, K=128) + gates ----------------
// grid (4, 512). Cols are gate-interleaved: global col = h*4+gate, CTA covers 32 H.
// Dynamic smem: staging As/Bs (2*128*36 floats) then reused as Ys[128][132].
__global__ void __launch_bounds__(256)
leaf_fused(const float* __restrict__ X, const float* __restrict__ c0,
           float* __restrict__ out_h, float* __restrict__ out_c) {
    extern __shared__ float sm[];
    float (*As)[36] = (float(*)[36])sm;
    float (*Bs)[36] = (float(*)[36])(sm + 128 * 36);
    float (*Ys)[132] = (float(*)[132])sm;

    int tid = threadIdx.x, wid = tid >> 5, lane = tid & 31;
    int gid = lane >> 2, tig = lane & 3;
    int wr = wid >> 2, wc = wid & 3;
    int rowBase = blockIdx.y * 128, colBase = blockIdx.x * 128;

    float acc[4][4][4];
#pragma unroll
    for (int mi = 0; mi < 4; mi++)
#pragma unroll
        for (int ni = 0; ni < 4; ni++)
#pragma unroll
            for (int q = 0; q < 4; q++) acc[mi][ni][q] = 0.f;

    for (int k0 = 0; k0 < 128; k0 += 32) {
#pragma unroll
        for (int it = tid; it < 1024; it += 256) {
            int r = it >> 3, q = it & 7;
            float4 v = *(const float4*)(X + (size_t)(rowBase + r) * 128 + k0 + q * 4);
            float4 u;
            u.x = __uint_as_float(f2tf(v.x)); u.y = __uint_as_float(f2tf(v.y));
            u.z = __uint_as_float(f2tf(v.z)); u.w = __uint_as_float(f2tf(v.w));
            *(float4*)&As[r][q * 4] = u;
        }
#pragma unroll
        for (int it = tid; it < 1024; it += 256) {
            int r = it >> 3, q = it & 7;
            float4 v = *(const float4*)(g_Mleaf + (size_t)(colBase + r) * 128 + k0 + q * 4);
            *(float4*)&Bs[r][q * 4] = v;
        }
        __syncthreads();
#pragma unroll
        for (int ks = 0; ks < 32; ks += 8) {
            uint32_t a[4][4], b[4][2];
#pragma unroll
            for (int mi = 0; mi < 4; mi++) {
                int r0 = wr * 64 + mi * 16 + gid;
                a[mi][0] = __float_as_uint(As[r0][ks + tig]);
                a[mi][1] = __float_as_uint(As[r0 + 8][ks + tig]);
                a[mi][2] = __float_as_uint(As[r0][ks + tig + 4]);
                a[mi][3] = __float_as_uint(As[r0 + 8][ks + tig + 4]);
            }
#pragma unroll
            for (int ni = 0; ni < 4; ni++) {
                int c0i = wc * 32 + ni * 8 + gid;
                b[ni][0] = __float_as_uint(Bs[c0i][ks + tig]);
                b[ni][1] = __float_as_uint(Bs[c0i][ks + tig + 4]);
            }
#pragma unroll
            for (int mi = 0; mi < 4; mi++)
#pragma unroll
                for (int ni = 0; ni < 4; ni++)
                    mma_tf32(acc[mi][ni], a[mi], b[ni]);
        }
        __syncthreads();
    }

    // spill acc (+ permuted bias) into Ys
#pragma unroll
    for (int mi = 0; mi < 4; mi++) {
        int row0 = wr * 64 + mi * 16 + gid;
#pragma unroll
        for (int ni = 0; ni < 4; ni++) {
            int col = wc * 32 + ni * 8 + tig * 2;
            float bx = g_bleaf[colBase + col], by = g_bleaf[colBase + col + 1];
            Ys[row0][col]     = acc[mi][ni][0] + bx;
            Ys[row0][col + 1] = acc[mi][ni][1] + by;
            Ys[row0 + 8][col]     = acc[mi][ni][2] + bx;
            Ys[row0 + 8][col + 1] = acc[mi][ni][3] + by;
        }
    }
    __syncthreads();

    // gates: thread t -> row = t>>1, H-halfgroup = (t&1)*16 (16 H indices each)
    int row = tid >> 1, hb0 = (tid & 1) * 16;
    int hgBase = blockIdx.x * 32;
    float hbuf[16], cbuf[16];
#pragma unroll
    for (int j = 0; j < 16; j++) {
        int hl = hb0 + j;
        int hg = hgBase + hl;
        float4 v = *(const float4*)&Ys[row][hl * 4];   // i, o, u, wf
        float c = sigf(v.x) * tanhf(v.z);
#pragma unroll
        for (int a = 0; a < 4; a++)
            c += sigf(v.w + g_cuf[a * 128 + hg]) * c0[a * 128 + hg];
        hbuf[j] = sigf(v.y) * tanhf(c);
        cbuf[j] = c;
    }
    float* ph = out_h + (size_t)(rowBase + row) * 128 + hgBase + hb0;
    float* pc = out_c + (size_t)(rowBase + row) * 128 + hgBase + hb0;
#pragma unroll
    for (int q = 0; q < 4; q++) {
        ((float4*)ph)[q] = make_float4(hbuf[q*4], hbuf[q*4+1], hbuf[q*4+2], hbuf[q*4+3]);
        ((float4*)pc)[q] = make_float4(cbuf[q*4], cbuf[q*4+1], cbuf[q*4+2], cbuf[q*4+3]);
    }
}

// ---------------- inner HMMA GEMM: Y[n x 896] = Z[n x 640] @ M^T + bias ----------------
__global__ void __launch_bounds__(256)
gemm_tc(const float* __restrict__ X, const float* __restrict__ Hp, int n) {
    const int K = 640, C = 896;
    __shared__ float As[128][36];
    __shared__ float Bs[128][36];

    int tid = threadIdx.x, wid = tid >> 5, lane = tid & 31;
    int gid = lane >> 2, tig = lane & 3;
    int wr = wid >> 2, wc = wid & 3;
    int rowBase = blockIdx.y * 128, colBase = blockIdx.x * 128;

    float acc[4][4][4];
#pragma unroll
    for (int mi = 0; mi < 4; mi++)
#pragma unroll
        for (int ni = 0; ni < 4; ni++)
#pragma unroll
            for (int q = 0; q < 4; q++) acc[mi][ni][q] = 0.f;

    for (int k0 = 0; k0 < K; k0 += 32) {
        const float* base; int pitch, koff;
        if (k0 < 128) { base = X;  pitch = 128; koff = k0; }
        else          { base = Hp; pitch = 512; koff = k0 - 128; }
#pragma unroll
        for (int it = tid; it < 1024; it += 256) {
            int r = it >> 3, q = it & 7;
            int row = rowBase + r;
            float4 v = make_float4(0.f, 0.f, 0.f, 0.f);
            if (row < n) v = *(const float4*)(base + (size_t)row * pitch + koff + q * 4);
            float4 u;
            u.x = __uint_as_float(f2tf(v.x)); u.y = __uint_as_float(f2tf(v.y));
            u.z = __uint_as_float(f2tf(v.z)); u.w = __uint_as_float(f2tf(v.w));
            *(float4*)&As[r][q * 4] = u;
        }
#pragma unroll
        for (int it = tid; it < 1024; it += 256) {
            int r = it >> 3, q = it & 7;
            float4 v = *(const float4*)(g_M + (size_t)(colBase + r) * K + k0 + q * 4);
            *(float4*)&Bs[r][q * 4] = v;
        }
        __syncthreads();
#pragma unroll
        for (int ks = 0; ks < 32; ks += 8) {
            uint32_t a[4][4], b[4][2];
#pragma unroll
            for (int mi = 0; mi < 4; mi++) {
                int r0 = wr * 64 + mi * 16 + gid;
                a[mi][0] = __float_as_uint(As[r0][ks + tig]);
                a[mi][1] = __float_as_uint(As[r0 + 8][ks + tig]);
                a[mi][2] = __float_as_uint(As[r0][ks + tig + 4]);
                a[mi][3] = __float_as_uint(As[r0 + 8][ks + tig + 4]);
            }
#pragma unroll
            for (int ni = 0; ni < 4; ni++) {
                int c0 = wc * 32 + ni * 8 + gid;
                b[ni][0] = __float_as_uint(Bs[c0][ks + tig]);
                b[ni][1] = __float_as_uint(Bs[c0][ks + tig + 4]);
            }
#pragma unroll
            for (int mi = 0; mi < 4; mi++)
#pragma unroll
                for (int ni = 0; ni < 4; ni++)
                    mma_tf32(acc[mi][ni], a[mi], b[ni]);
        }
        __syncthreads();
    }

#pragma unroll
    for (int mi = 0; mi < 4; mi++) {
        int row0 = rowBase + wr * 64 + mi * 16 + gid;
#pragma unroll
        for (int ni = 0; ni < 4; ni++) {
            int col = colBase + wc * 32 + ni * 8 + tig * 2;
            float bx = g_bias[col], by = g_bias[col + 1];
            if (row0 < n) {
                float2 o = make_float2(acc[mi][ni][0] + bx, acc[mi][ni][1] + by);
                *(float2*)&g_Y[(size_t)row0 * C + col] = o;
            }
            if (row0 + 8 < n) {
                float2 o = make_float2(acc[mi][ni][2] + bx, acc[mi][ni][3] + by);
                *(float2*)&g_Y[(size_t)(row0 + 8) * C + col] = o;
            }
        }
    }
}

// ---------------- elementwise: inner levels ----------------
__global__ void inner_elem_kernel(const float* __restrict__ cprev,
                                  float* __restrict__ out_h, float* __restrict__ out_c, int n) {
    int j = blockIdx.x;
    if (j >= n) return;
    int r = threadIdx.x;
    const float* Yr = g_Y + (size_t)j * 896;
    float iv = Yr[r], ov = Yr[128 + r], uv = Yr[256 + r];
    float c = sigf(iv) * tanhf(uv);
#pragma unroll
    for (int a = 0; a < 4; a++)
        c += sigf(Yr[384 + a * 128 + r]) * cprev[(size_t)(4 * j + a) * 128 + r];
    float h = sigf(ov) * tanhf(c);
    out_h[(size_t)j * 128 + r] = h;
    out_c[(size_t)j * 128 + r] = c;
}

// ---------------- launch ----------------
extern "C" void kernel_launch(void* const* d_in, const int* in_sizes, int n_in,
                              void* d_out, int out_size) {
    const float* emb    = (const float*)d_in[0];
    const float* W_iou  = (const float*)d_in[1];
    const float* b_iou  = (const float*)d_in[2];
    const float* U_iou  = (const float*)d_in[3];
    const float* b_uiou = (const float*)d_in[4];
    const float* W_f    = (const float*)d_in[5];
    const float* b_wf   = (const float*)d_in[6];
    const float* U_f    = (const float*)d_in[7];
    const float* b_uf   = (const float*)d_in[8];
    const float* h0     = (const float*)d_in[9];
    const float* c0     = (const float*)d_in[10];

    float* out_h = (float*)d_out;
    float* out_c = out_h + (size_t)NN * 128;

    static int smem_set = 0;
    if (!smem_set) {
        cudaFuncSetAttribute(leaf_fused, cudaFuncAttributeMaxDynamicSharedMemorySize,
                             128 * 132 * 4);
        smem_set = 1;
    }

    prep_M_kernel<<<512, 256>>>(W_iou, U_iou, b_iou, b_uiou, W_f, U_f, b_wf, b_uf);
    prep_const_kernel<<<7, 128>>>(U_iou, b_iou, b_uiou, U_f, b_uf, h0, b_wf);

    const int lev_n[9] = {65536, 16384, 4096, 1024, 256, 64, 16, 4, 1};
    int offs[10];
    offs[0] = 0;
    for (int i = 0; i < 9; i++) offs[i + 1] = offs[i] + lev_n[i];

    // leaf level: fully fused
    leaf_fused<<<dim3(4, NLEAF / 128), 256, 128 * 132 * 4>>>(emb, c0, out_h, out_c);

    // inner levels 7..0 (C=896, K=640)
    for (int i = 1; i < 9; i++) {
        int n = lev_n[i];
        const float* X  = emb   + (size_t)offs[i]     * 128;
        const float* Hp = out_h + (size_t)offs[i - 1] * 128;
        const float* Cp = out_c + (size_t)offs[i - 1] * 128;
        gemm_tc<<<dim3(7, (n + 127) / 128), 256>>>(X, Hp, n);
        inner_elem_kernel<<<n, 128>>>(Cp, out_h + (size_t)offs[i] * 128,
                                      out_c + (size_t)offs[i] * 128, n);
    }
}

// round 9
// speedup vs baseline: 1.1293x; 1.1293x over previous
#include <cuda_runtime.h>
#include <math.h>
#include <stdint.h>

// Tree-LSTM, 4-ary, depth 8. E=H=128, A=4. N_NODES=87381, leaves=65536.
// R9: cp.async 2-stage pipelined HMMA tf32 GEMMs.
//  - leaf: fused GEMM+gates, B resident in smem (loaded once), A pipelined.
//  - inner: A+B pipelined, 20 K-chunks.

#define NN     87381
#define NLEAF  65536

// ---------------- scratch ----------------
__device__ float g_Y[(size_t)16384 * 896];   // inner-level GEMM output only
__device__ float g_M[896 * 640];             // inner combined weight (tf32-rounded)
__device__ float g_bias[896];
__device__ float g_Mleaf[512 * 128];         // leaf weight, PERMUTED col = h*4+gate
__device__ float g_bleaf[512];               // leaf bias, PERMUTED
__device__ float g_cuf[512];                 // leaf f-gate const U_f@h0+b_uf (a*128+h)

__device__ __forceinline__ float sigf(float x) { return 1.0f / (1.0f + expf(-x)); }
__device__ __forceinline__ uint32_t f2tf(float f) {
    uint32_t r; asm("cvt.rna.tf32.f32 %0, %1;" : "=r"(r) : "f"(f)); return r;
}
__device__ __forceinline__ void cp16(uint32_t dst, const void* src, uint32_t srcsz) {
    asm volatile("cp.async.ca.shared.global [%0], [%1], 16, %2;"
                 :: "r"(dst), "l"(src), "r"(srcsz));
}
#define CP_COMMIT() asm volatile("cp.async.commit_group;" ::: "memory")
#define CP_WAIT(N)  asm volatile("cp.async.wait_group %0;" :: "n"(N) : "memory")

// ---------------- prep ----------------
__global__ void prep_M_kernel(const float* __restrict__ W_iou, const float* __restrict__ U_iou,
                              const float* __restrict__ b_iou, const float* __restrict__ b_uiou,
                              const float* __restrict__ W_f,  const float* __restrict__ U_f,
                              const float* __restrict__ b_wf, const float* __restrict__ b_uf) {
    int stride = gridDim.x * blockDim.x;
    int idx = blockIdx.x * blockDim.x + threadIdx.x;
    for (int t = idx; t < 896 * 640; t += stride) {
        int c = t / 640, k = t - c * 640;
        float v;
        if (c < 384) v = (k < 128) ? W_iou[c * 128 + k] : U_iou[c * 512 + (k - 128)];
        else {
            int cc = c - 384;
            v = (k < 128) ? W_f[(cc & 127) * 128 + k] : U_f[cc * 512 + (k - 128)];
        }
        g_M[t] = __uint_as_float(f2tf(v));
    }
    // leaf weight, permuted: col c = h*4+g ; g<3 -> W_iou[g*128+h], g=3 -> W_f[h]
    for (int t = idx; t < 512 * 128; t += stride) {
        int c = t >> 7, k = t & 127;
        int h = c >> 2, g = c & 3;
        float v = (g < 3) ? W_iou[(g * 128 + h) * 128 + k] : W_f[h * 128 + k];
        g_Mleaf[t] = __uint_as_float(f2tf(v));
    }
    if (idx < 896)
        g_bias[idx] = (idx < 384) ? (b_iou[idx] + b_uiou[idx])
                                  : (b_wf[(idx - 384) & 127] + b_uf[idx - 384]);
}

__global__ void prep_const_kernel(const float* __restrict__ U_iou, const float* __restrict__ b_iou,
                                  const float* __restrict__ b_uiou, const float* __restrict__ U_f,
                                  const float* __restrict__ b_uf, const float* __restrict__ h0,
                                  const float* __restrict__ b_wf) {
    int c = blockIdx.x * blockDim.x + threadIdx.x;
    if (c < 384) {
        int g = c >> 7, h = c & 127;
        float s = b_iou[c] + b_uiou[c];
        for (int k = 0; k < 512; k++) s += U_iou[c * 512 + k] * h0[k];
        g_bleaf[h * 4 + g] = s;
    } else if (c < 896) {
        int cc = c - 384;
        float s = b_uf[cc];
        for (int k = 0; k < 512; k++) s += U_f[cc * 512 + k] * h0[k];
        g_cuf[cc] = s;
        if (cc < 128) g_bleaf[cc * 4 + 3] = b_wf[cc];
    }
}

// ---------------- mma helper ----------------
__device__ __forceinline__ void mma_tf32(float* c, const uint32_t* a, const uint32_t* b) {
    asm volatile(
        "mma.sync.aligned.m16n8k8.row.col.f32.tf32.tf32.f32 "
        "{%0,%1,%2,%3}, {%4,%5,%6,%7}, {%8,%9}, {%0,%1,%2,%3};"
        : "+f"(c[0]), "+f"(c[1]), "+f"(c[2]), "+f"(c[3])
        : "r"(a[0]), "r"(a[1]), "r"(a[2]), "r"(a[3]), "r"(b[0]), "r"(b[1]));
}

// ---------------- fused leaf: pipelined HMMA GEMM (128x128, K=128) + gates ----------------
// smem floats: As[2][128][36] at 0..9216, B/Ys [128][132] at 9216..26112 (104.4KB)
__global__ void __launch_bounds__(256, 2)
leaf_fused(const float* __restrict__ X, const float* __restrict__ c0,
           float* __restrict__ out_h, float* __restrict__ out_c) {
    extern __shared__ float sm[];
    float* Asb = sm;            // staged A
    float* Bsb = sm + 9216;     // resident B, reused as Ys
    uint32_t sbase = (uint32_t)__cvta_generic_to_shared(sm);

    int tid = threadIdx.x, wid = tid >> 5, lane = tid & 31;
    int gid = lane >> 2, tig = lane & 3;
    int wr = wid >> 2, wc = wid & 3;
    int rowBase = blockIdx.y * 128, colBase = blockIdx.x * 128;

    float acc[4][4][4];
#pragma unroll
    for (int mi = 0; mi < 4; mi++)
#pragma unroll
        for (int ni = 0; ni < 4; ni++)
#pragma unroll
            for (int q = 0; q < 4; q++) acc[mi][ni][q] = 0.f;

    // resident B load (once): 128 cols x 128 K
#pragma unroll
    for (int it = tid; it < 4096; it += 256) {
        int r = it >> 5, q = (it & 31) * 4;
        cp16(sbase + ((9216 + r * 132 + q) << 2),
             g_Mleaf + (size_t)(colBase + r) * 128 + q, 16);
    }
    // A chunk 0
#pragma unroll
    for (int it = tid; it < 1024; it += 256) {
        int r = it >> 3, q = (it & 7) * 4;
        cp16(sbase + ((r * 36 + q) << 2),
             X + (size_t)(rowBase + r) * 128 + q, 16);
    }
    CP_COMMIT();

    for (int kc = 0; kc < 4; kc++) {
        int cur = kc & 1;
        if (kc < 3) {
            int st = cur ^ 1;
#pragma unroll
            for (int it = tid; it < 1024; it += 256) {
                int r = it >> 3, q = (it & 7) * 4;
                cp16(sbase + (((st * 128 + r) * 36 + q) << 2),
                     X + (size_t)(rowBase + r) * 128 + (kc + 1) * 32 + q, 16);
            }
            CP_COMMIT();
            CP_WAIT(1);
        } else {
            CP_WAIT(0);
        }
        __syncthreads();
#pragma unroll
        for (int ks = 0; ks < 32; ks += 8) {
            uint32_t a[4][4], b[4][2];
#pragma unroll
            for (int mi = 0; mi < 4; mi++) {
                const float* Ar = Asb + (cur * 128 + wr * 64 + mi * 16 + gid) * 36;
                a[mi][0] = f2tf(Ar[ks + tig]);
                a[mi][1] = f2tf(Ar[8 * 36 + ks + tig]);
                a[mi][2] = f2tf(Ar[ks + tig + 4]);
                a[mi][3] = f2tf(Ar[8 * 36 + ks + tig + 4]);
            }
#pragma unroll
            for (int ni = 0; ni < 4; ni++) {
                const float* Br = Bsb + (wc * 32 + ni * 8 + gid) * 132 + kc * 32;
                b[ni][0] = __float_as_uint(Br[ks + tig]);
                b[ni][1] = __float_as_uint(Br[ks + tig + 4]);
            }
#pragma unroll
            for (int mi = 0; mi < 4; mi++)
#pragma unroll
                for (int ni = 0; ni < 4; ni++)
                    mma_tf32(acc[mi][ni], a[mi], b[ni]);
        }
        __syncthreads();
    }

    // spill acc (+ permuted bias) into Ys (reuses B region)
    float (*Ys)[132] = (float(*)[132])Bsb;
#pragma unroll
    for (int mi = 0; mi < 4; mi++) {
        int row0 = wr * 64 + mi * 16 + gid;
#pragma unroll
        for (int ni = 0; ni < 4; ni++) {
            int col = wc * 32 + ni * 8 + tig * 2;
            float bx = g_bleaf[colBase + col], by = g_bleaf[colBase + col + 1];
            Ys[row0][col]         = acc[mi][ni][0] + bx;
            Ys[row0][col + 1]     = acc[mi][ni][1] + by;
            Ys[row0 + 8][col]     = acc[mi][ni][2] + bx;
            Ys[row0 + 8][col + 1] = acc[mi][ni][3] + by;
        }
    }
    __syncthreads();

    // gates: thread t -> row = t>>1, 16 H indices
    int row = tid >> 1, hb0 = (tid & 1) * 16;
    int hgBase = blockIdx.x * 32;
    float hbuf[16], cbuf[16];
#pragma unroll
    for (int j = 0; j < 16; j++) {
        int hl = hb0 + j;
        int hg = hgBase + hl;
        float4 v = *(const float4*)&Ys[row][hl * 4];   // i, o, u, wf
        float c = sigf(v.x) * tanhf(v.z);
#pragma unroll
        for (int a = 0; a < 4; a++)
            c += sigf(v.w + g_cuf[a * 128 + hg]) * c0[a * 128 + hg];
        hbuf[j] = sigf(v.y) * tanhf(c);
        cbuf[j] = c;
    }
    float* ph = out_h + (size_t)(rowBase + row) * 128 + hgBase + hb0;
    float* pc = out_c + (size_t)(rowBase + row) * 128 + hgBase + hb0;
#pragma unroll
    for (int q = 0; q < 4; q++) {
        ((float4*)ph)[q] = make_float4(hbuf[q*4], hbuf[q*4+1], hbuf[q*4+2], hbuf[q*4+3]);
        ((float4*)pc)[q] = make_float4(cbuf[q*4], cbuf[q*4+1], cbuf[q*4+2], cbuf[q*4+3]);
    }
}

// ---------------- inner pipelined GEMM: Y[n x 896] = Z[n x 640] @ M^T + bias ----------------
// smem floats: As[2][128][36] at 0..9216, Bs[2][128][36] at 9216..18432 (73.7KB)
__global__ void __launch_bounds__(256, 2)
gemm_tc(const float* __restrict__ X, const float* __restrict__ Hp, int n) {
    extern __shared__ float sm[];
    float* Asb = sm;
    float* Bsb = sm + 9216;
    uint32_t sbase = (uint32_t)__cvta_generic_to_shared(sm);

    int tid = threadIdx.x, wid = tid >> 5, lane = tid & 31;
    int gid = lane >> 2, tig = lane & 3;
    int wr = wid >> 2, wc = wid & 3;
    int rowBase = blockIdx.y * 128, colBase = blockIdx.x * 128;

    float acc[4][4][4];
#pragma unroll
    for (int mi = 0; mi < 4; mi++)
#pragma unroll
        for (int ni = 0; ni < 4; ni++)
#pragma unroll
            for (int q = 0; q < 4; q++) acc[mi][ni][q] = 0.f;

    auto loadAB = [&](int kc, int st) {
        int k0 = kc * 32;
        const float* base; int pitch, koff;
        if (k0 < 128) { base = X;  pitch = 128; koff = k0; }
        else          { base = Hp; pitch = 512; koff = k0 - 128; }
#pragma unroll
        for (int it = tid; it < 1024; it += 256) {
            int r = it >> 3, q = (it & 7) * 4;
            int row = rowBase + r;
            cp16(sbase + (((st * 128 + r) * 36 + q) << 2),
                 base + (size_t)row * pitch + koff + q, (row < n) ? 16u : 0u);
        }
#pragma unroll
        for (int it = tid; it < 1024; it += 256) {
            int r = it >> 3, q = (it & 7) * 4;
            cp16(sbase + ((9216 + (st * 128 + r) * 36 + q) << 2),
                 g_M + (size_t)(colBase + r) * 640 + k0 + q, 16);
        }
    };

    loadAB(0, 0);
    CP_COMMIT();

    for (int kc = 0; kc < 20; kc++) {
        int cur = kc & 1;
        if (kc < 19) {
            loadAB(kc + 1, cur ^ 1);
            CP_COMMIT();
            CP_WAIT(1);
        } else {
            CP_WAIT(0);
        }
        __syncthreads();
#pragma unroll
        for (int ks = 0; ks < 32; ks += 8) {
            uint32_t a[4][4], b[4][2];
#pragma unroll
            for (int mi = 0; mi < 4; mi++) {
                const float* Ar = Asb + (cur * 128 + wr * 64 + mi * 16 + gid) * 36;
                a[mi][0] = f2tf(Ar[ks + tig]);
                a[mi][1] = f2tf(Ar[8 * 36 + ks + tig]);
                a[mi][2] = f2tf(Ar[ks + tig + 4]);
                a[mi][3] = f2tf(Ar[8 * 36 + ks + tig + 4]);
            }
#pragma unroll
            for (int ni = 0; ni < 4; ni++) {
                const float* Br = Bsb + (cur * 128 + wc * 32 + ni * 8 + gid) * 36;
                b[ni][0] = __float_as_uint(Br[ks + tig]);
                b[ni][1] = __float_as_uint(Br[ks + tig + 4]);
            }
#pragma unroll
            for (int mi = 0; mi < 4; mi++)
#pragma unroll
                for (int ni = 0; ni < 4; ni++)
                    mma_tf32(acc[mi][ni], a[mi], b[ni]);
        }
        __syncthreads();
    }

#pragma unroll
    for (int mi = 0; mi < 4; mi++) {
        int row0 = rowBase + wr * 64 + mi * 16 + gid;
#pragma unroll
        for (int ni = 0; ni < 4; ni++) {
            int col = colBase + wc * 32 + ni * 8 + tig * 2;
            float bx = g_bias[col], by = g_bias[col + 1];
            if (row0 < n) {
                float2 o = make_float2(acc[mi][ni][0] + bx, acc[mi][ni][1] + by);
                *(float2*)&g_Y[(size_t)row0 * 896 + col] = o;
            }
            if (row0 + 8 < n) {
                float2 o = make_float2(acc[mi][ni][2] + bx, acc[mi][ni][3] + by);
                *(float2*)&g_Y[(size_t)(row0 + 8) * 896 + col] = o;
            }
        }
    }
}

// ---------------- elementwise: inner levels ----------------
__global__ void inner_elem_kernel(const float* __restrict__ cprev,
                                  float* __restrict__ out_h, float* __restrict__ out_c, int n) {
    int j = blockIdx.x;
    if (j >= n) return;
    int r = threadIdx.x;
    const float* Yr = g_Y + (size_t)j * 896;
    float iv = Yr[r], ov = Yr[128 + r], uv = Yr[256 + r];
    float c = sigf(iv) * tanhf(uv);
#pragma unroll
    for (int a = 0; a < 4; a++)
        c += sigf(Yr[384 + a * 128 + r]) * cprev[(size_t)(4 * j + a) * 128 + r];
    float h = sigf(ov) * tanhf(c);
    out_h[(size_t)j * 128 + r] = h;
    out_c[(size_t)j * 128 + r] = c;
}

// ---------------- launch ----------------
extern "C" void kernel_launch(void* const* d_in, const int* in_sizes, int n_in,
                              void* d_out, int out_size) {
    const float* emb    = (const float*)d_in[0];
    const float* W_iou  = (const float*)d_in[1];
    const float* b_iou  = (const float*)d_in[2];
    const float* U_iou  = (const float*)d_in[3];
    const float* b_uiou = (const float*)d_in[4];
    const float* W_f    = (const float*)d_in[5];
    const float* b_wf   = (const float*)d_in[6];
    const float* U_f    = (const float*)d_in[7];
    const float* b_uf   = (const float*)d_in[8];
    const float* h0     = (const float*)d_in[9];
    const float* c0     = (const float*)d_in[10];

    float* out_h = (float*)d_out;
    float* out_c = out_h + (size_t)NN * 128;

    cudaFuncSetAttribute(leaf_fused, cudaFuncAttributeMaxDynamicSharedMemorySize, 26112 * 4);
    cudaFuncSetAttribute(gemm_tc,    cudaFuncAttributeMaxDynamicSharedMemorySize, 18432 * 4);

    prep_M_kernel<<<512, 256>>>(W_iou, U_iou, b_iou, b_uiou, W_f, U_f, b_wf, b_uf);
    prep_const_kernel<<<7, 128>>>(U_iou, b_iou, b_uiou, U_f, b_uf, h0, b_wf);

    const int lev_n[9] = {65536, 16384, 4096, 1024, 256, 64, 16, 4, 1};
    int offs[10];
    offs[0] = 0;
    for (int i = 0; i < 9; i++) offs[i + 1] = offs[i] + lev_n[i];

    // leaf level: fully fused, pipelined
    leaf_fused<<<dim3(4, NLEAF / 128), 256, 26112 * 4>>>(emb, c0, out_h, out_c);

    // inner levels 7..0 (C=896, K=640)
    for (int i = 1; i < 9; i++) {
        int n = lev_n[i];
        const float* X  = emb   + (size_t)offs[i]     * 128;
        const float* Hp = out_h + (size_t)offs[i - 1] * 128;
        const float* Cp = out_c + (size_t)offs[i - 1] * 128;
        gemm_tc<<<dim3(7, (n + 127) / 128), 256, 18432 * 4>>>(X, Hp, n);
        inner_elem_kernel<<<n, 128>>>(Cp, out_h + (size_t)offs[i] * 128,
                                      out_c + (size_t)offs[i] * 128, n);
    }
}

// round 10
// speedup vs baseline: 1.2009x; 1.0634x over previous
#include <cuda_runtime.h>
#include <math.h>
#include <stdint.h>

// Tree-LSTM, 4-ary, depth 8. E=H=128, A=4. N_NODES=87381, leaves=65536.
// R10: persistent-M fused leaf — B resident (loaded once per CTA), A cp.async
// double-buffered ACROSS row tiles (no pipeline drain), epilogue in 4 column
// quarters through the freed A stage. Inner levels unchanged from R9.

#define NN     87381
#define NLEAF  65536

// ---------------- scratch ----------------
__device__ float g_Y[(size_t)16384 * 896];   // inner-level GEMM output only
__device__ float g_M[896 * 640];             // inner combined weight (tf32-rounded)
__device__ float g_bias[896];
__device__ float g_Mleaf[512 * 128];         // leaf weight, PERMUTED col = h*4+gate
__device__ float g_bleaf[512];               // leaf bias, PERMUTED
__device__ float g_cuf[512];                 // leaf f-gate const U_f@h0+b_uf (a*128+h)

__device__ __forceinline__ float sigf(float x) { return 1.0f / (1.0f + expf(-x)); }
__device__ __forceinline__ uint32_t f2tf(float f) {
    uint32_t r; asm("cvt.rna.tf32.f32 %0, %1;" : "=r"(r) : "f"(f)); return r;
}
__device__ __forceinline__ void cp16(uint32_t dst, const void* src, uint32_t srcsz) {
    asm volatile("cp.async.ca.shared.global [%0], [%1], 16, %2;"
                 :: "r"(dst), "l"(src), "r"(srcsz));
}
#define CP_COMMIT() asm volatile("cp.async.commit_group;" ::: "memory")
#define CP_WAIT(N)  asm volatile("cp.async.wait_group %0;" :: "n"(N) : "memory")

// ---------------- prep ----------------
__global__ void prep_M_kernel(const float* __restrict__ W_iou, const float* __restrict__ U_iou,
                              const float* __restrict__ b_iou, const float* __restrict__ b_uiou,
                              const float* __restrict__ W_f,  const float* __restrict__ U_f,
                              const float* __restrict__ b_wf, const float* __restrict__ b_uf) {
    int stride = gridDim.x * blockDim.x;
    int idx = blockIdx.x * blockDim.x + threadIdx.x;
    for (int t = idx; t < 896 * 640; t += stride) {
        int c = t / 640, k = t - c * 640;
        float v;
        if (c < 384) v = (k < 128) ? W_iou[c * 128 + k] : U_iou[c * 512 + (k - 128)];
        else {
            int cc = c - 384;
            v = (k < 128) ? W_f[(cc & 127) * 128 + k] : U_f[cc * 512 + (k - 128)];
        }
        g_M[t] = __uint_as_float(f2tf(v));
    }
    // leaf weight, permuted: col c = h*4+g ; g<3 -> W_iou[g*128+h], g=3 -> W_f[h]
    for (int t = idx; t < 512 * 128; t += stride) {
        int c = t >> 7, k = t & 127;
        int h = c >> 2, g = c & 3;
        float v = (g < 3) ? W_iou[(g * 128 + h) * 128 + k] : W_f[h * 128 + k];
        g_Mleaf[t] = __uint_as_float(f2tf(v));
    }
    if (idx < 896)
        g_bias[idx] = (idx < 384) ? (b_iou[idx] + b_uiou[idx])
                                  : (b_wf[(idx - 384) & 127] + b_uf[idx - 384]);
}

__global__ void prep_const_kernel(const float* __restrict__ U_iou, const float* __restrict__ b_iou,
                                  const float* __restrict__ b_uiou, const float* __restrict__ U_f,
                                  const float* __restrict__ b_uf, const float* __restrict__ h0,
                                  const float* __restrict__ b_wf) {
    int c = blockIdx.x * blockDim.x + threadIdx.x;
    if (c < 384) {
        int g = c >> 7, h = c & 127;
        float s = b_iou[c] + b_uiou[c];
        for (int k = 0; k < 512; k++) s += U_iou[c * 512 + k] * h0[k];
        g_bleaf[h * 4 + g] = s;
    } else if (c < 896) {
        int cc = c - 384;
        float s = b_uf[cc];
        for (int k = 0; k < 512; k++) s += U_f[cc * 512 + k] * h0[k];
        g_cuf[cc] = s;
        if (cc < 128) g_bleaf[cc * 4 + 3] = b_wf[cc];
    }
}

// ---------------- mma helper ----------------
__device__ __forceinline__ void mma_tf32(float* c, const uint32_t* a, const uint32_t* b) {
    asm volatile(
        "mma.sync.aligned.m16n8k8.row.col.f32.tf32.tf32.f32 "
        "{%0,%1,%2,%3}, {%4,%5,%6,%7}, {%8,%9}, {%0,%1,%2,%3};"
        : "+f"(c[0]), "+f"(c[1]), "+f"(c[2]), "+f"(c[3])
        : "r"(a[0]), "r"(a[1]), "r"(a[2]), "r"(a[3]), "r"(b[0]), "r"(b[1]));
}

// ---------------- persistent fused leaf ----------------
// grid (4 colTiles, 74). smem floats:
//   As[2][128][36]  : 0 .. 9216       (stage1 reused as epilogue quarter buffer)
//   B  [128][132]   : 9216 .. 26112   (resident, loaded once)
//   c0s[512]        : 26112 .. 26624
//   cufs[512]       : 26624 .. 27136
//   bls[512]        : 27136 .. 27648   (110.6KB total, 2 CTAs/SM)
__global__ void __launch_bounds__(256, 2)
leaf_fused(const float* __restrict__ X, const float* __restrict__ c0,
           float* __restrict__ out_h, float* __restrict__ out_c) {
    extern __shared__ float sm[];
    uint32_t sbase = (uint32_t)__cvta_generic_to_shared(sm);
    const int B_OFF = 9216, C0_OFF = 26112, CUF_OFF = 26624, BL_OFF = 27136;

    int tid = threadIdx.x, wid = tid >> 5, lane = tid & 31;
    int gid = lane >> 2, tig = lane & 3;
    int wr = wid >> 2, wc = wid & 3;
    int colBase = blockIdx.x * 128;
    int hgBase = blockIdx.x * 32;

    // resident B (128 cols x 128 K, pitch 132) + consts
#pragma unroll 4
    for (int it = tid; it < 4096; it += 256) {
        int r = it >> 5, q = (it & 31) * 4;
        cp16(sbase + ((B_OFF + r * 132 + q) << 2),
             g_Mleaf + (size_t)(colBase + r) * 128 + q, 16);
    }
    if (tid < 128) {
        cp16(sbase + ((C0_OFF  + tid * 4) << 2), c0      + tid * 4, 16);
        cp16(sbase + ((CUF_OFF + tid * 4) << 2), g_cuf   + tid * 4, 16);
        cp16(sbase + ((BL_OFF  + tid * 4) << 2), g_bleaf + tid * 4, 16);
    }
    CP_COMMIT();

    auto loadA = [&](int rt, int kc, int st) {
        const float* src = X + (size_t)rt * 128 * 128 + kc * 32;
#pragma unroll
        for (int it = tid; it < 1024; it += 256) {
            int r = it >> 3, q = (it & 7) * 4;
            cp16(sbase + (((st * 128 + r) * 36 + q) << 2), src + (size_t)r * 128 + q, 16);
        }
    };

    loadA(blockIdx.y, 0, 0);
    CP_COMMIT();

    for (int rt = blockIdx.y; rt < 512; rt += 74) {
        loadA(rt, 1, 1);
        CP_COMMIT();

        float acc[4][4][4];
#pragma unroll
        for (int mi = 0; mi < 4; mi++)
#pragma unroll
            for (int ni = 0; ni < 4; ni++)
#pragma unroll
                for (int q = 0; q < 4; q++) acc[mi][ni][q] = 0.f;

#pragma unroll
        for (int kc = 0; kc < 4; kc++) {
            CP_WAIT(1);
            __syncthreads();
            int cur = kc & 1;
#pragma unroll
            for (int ks = 0; ks < 32; ks += 8) {
                uint32_t a[4][4], b[4][2];
#pragma unroll
                for (int mi = 0; mi < 4; mi++) {
                    const float* Ar = sm + (cur * 128 + wr * 64 + mi * 16 + gid) * 36;
                    a[mi][0] = f2tf(Ar[ks + tig]);
                    a[mi][1] = f2tf(Ar[8 * 36 + ks + tig]);
                    a[mi][2] = f2tf(Ar[ks + tig + 4]);
                    a[mi][3] = f2tf(Ar[8 * 36 + ks + tig + 4]);
                }
#pragma unroll
                for (int ni = 0; ni < 4; ni++) {
                    const float* Br = sm + B_OFF + (wc * 32 + ni * 8 + gid) * 132 + kc * 32;
                    b[ni][0] = __float_as_uint(Br[ks + tig]);
                    b[ni][1] = __float_as_uint(Br[ks + tig + 4]);
                }
#pragma unroll
                for (int mi = 0; mi < 4; mi++)
#pragma unroll
                    for (int ni = 0; ni < 4; ni++)
                        mma_tf32(acc[mi][ni], a[mi], b[ni]);
            }
            __syncthreads();
            if (kc < 2) {
                loadA(rt, kc + 2, cur);
                CP_COMMIT();
            } else if (kc == 2) {
                int nrt = rt + 74; if (nrt >= 512) nrt = 0;   // clamped dummy on last tile
                loadA(nrt, 0, 0);
                CP_COMMIT();
            }
        }

        // ---- epilogue: 4 column quarters through stage 1 (pitch 36) ----
        float (*Ysq)[36] = (float(*)[36])(sm + 4608);
        int rowBaseG = rt * 128;
        int row = tid >> 1, hq = (tid & 1) * 4;
#pragma unroll
        for (int wq = 0; wq < 4; wq++) {
            if (wc == wq) {
#pragma unroll
                for (int mi = 0; mi < 4; mi++) {
                    int r0 = wr * 64 + mi * 16 + gid;
#pragma unroll
                    for (int ni = 0; ni < 4; ni++) {
                        int col = ni * 8 + tig * 2;
                        float bx = sm[BL_OFF + colBase + wq * 32 + col];
                        float by = sm[BL_OFF + colBase + wq * 32 + col + 1];
                        Ysq[r0][col]         = acc[mi][ni][0] + bx;
                        Ysq[r0][col + 1]     = acc[mi][ni][1] + by;
                        Ysq[r0 + 8][col]     = acc[mi][ni][2] + bx;
                        Ysq[r0 + 8][col + 1] = acc[mi][ni][3] + by;
                    }
                }
            }
            __syncthreads();
            float hb[4], cb[4];
#pragma unroll
            for (int j = 0; j < 4; j++) {
                int hl = hq + j;
                float4 v = *(const float4*)&Ysq[row][hl * 4];   // i, o, u, wf
                int hg = hgBase + wq * 8 + hl;
                float cc = sigf(v.x) * tanhf(v.z);
#pragma unroll
                for (int a = 0; a < 4; a++)
                    cc += sigf(v.w + sm[CUF_OFF + a * 128 + hg]) * sm[C0_OFF + a * 128 + hg];
                hb[j] = sigf(v.y) * tanhf(cc);
                cb[j] = cc;
            }
            size_t ob = (size_t)(rowBaseG + row) * 128 + hgBase + wq * 8 + hq;
            *(float4*)(out_h + ob) = make_float4(hb[0], hb[1], hb[2], hb[3]);
            *(float4*)(out_c + ob) = make_float4(cb[0], cb[1], cb[2], cb[3]);
            __syncthreads();
        }
    }
}

// ---------------- inner pipelined GEMM (unchanged from R9) ----------------
__global__ void __launch_bounds__(256, 2)
gemm_tc(const float* __restrict__ X, const float* __restrict__ Hp, int n) {
    extern __shared__ float sm[];
    float* Asb = sm;
    float* Bsb = sm + 9216;
    uint32_t sbase = (uint32_t)__cvta_generic_to_shared(sm);

    int tid = threadIdx.x, wid = tid >> 5, lane = tid & 31;
    int gid = lane >> 2, tig = lane & 3;
    int wr = wid >> 2, wc = wid & 3;
    int rowBase = blockIdx.y * 128, colBase = blockIdx.x * 128;

    float acc[4][4][4];
#pragma unroll
    for (int mi = 0; mi < 4; mi++)
#pragma unroll
        for (int ni = 0; ni < 4; ni++)
#pragma unroll
            for (int q = 0; q < 4; q++) acc[mi][ni][q] = 0.f;

    auto loadAB = [&](int kc, int st) {
        int k0 = kc * 32;
        const float* base; int pitch, koff;
        if (k0 < 128) { base = X;  pitch = 128; koff = k0; }
        else          { base = Hp; pitch = 512; koff = k0 - 128; }
#pragma unroll
        for (int it = tid; it < 1024; it += 256) {
            int r = it >> 3, q = (it & 7) * 4;
            int row = rowBase + r;
            cp16(sbase + (((st * 128 + r) * 36 + q) << 2),
                 base + (size_t)row * pitch + koff + q, (row < n) ? 16u : 0u);
        }
#pragma unroll
        for (int it = tid; it < 1024; it += 256) {
            int r = it >> 3, q = (it & 7) * 4;
            cp16(sbase + ((9216 + (st * 128 + r) * 36 + q) << 2),
                 g_M + (size_t)(colBase + r) * 640 + k0 + q, 16);
        }
    };

    loadAB(0, 0);
    CP_COMMIT();

    for (int kc = 0; kc < 20; kc++) {
        int cur = kc & 1;
        if (kc < 19) {
            loadAB(kc + 1, cur ^ 1);
            CP_COMMIT();
            CP_WAIT(1);
        } else {
            CP_WAIT(0);
        }
        __syncthreads();
#pragma unroll
        for (int ks = 0; ks < 32; ks += 8) {
            uint32_t a[4][4], b[4][2];
#pragma unroll
            for (int mi = 0; mi < 4; mi++) {
                const float* Ar = Asb + (cur * 128 + wr * 64 + mi * 16 + gid) * 36;
                a[mi][0] = f2tf(Ar[ks + tig]);
                a[mi][1] = f2tf(Ar[8 * 36 + ks + tig]);
                a[mi][2] = f2tf(Ar[ks + tig + 4]);
                a[mi][3] = f2tf(Ar[8 * 36 + ks + tig + 4]);
            }
#pragma unroll
            for (int ni = 0; ni < 4; ni++) {
                const float* Br = Bsb + (cur * 128 + wc * 32 + ni * 8 + gid) * 36;
                b[ni][0] = __float_as_uint(Br[ks + tig]);
                b[ni][1] = __float_as_uint(Br[ks + tig + 4]);
            }
#pragma unroll
            for (int mi = 0; mi < 4; mi++)
#pragma unroll
                for (int ni = 0; ni < 4; ni++)
                    mma_tf32(acc[mi][ni], a[mi], b[ni]);
        }
        __syncthreads();
    }

#pragma unroll
    for (int mi = 0; mi < 4; mi++) {
        int row0 = rowBase + wr * 64 + mi * 16 + gid;
#pragma unroll
        for (int ni = 0; ni < 4; ni++) {
            int col = colBase + wc * 32 + ni * 8 + tig * 2;
            float bx = g_bias[col], by = g_bias[col + 1];
            if (row0 < n) {
                float2 o = make_float2(acc[mi][ni][0] + bx, acc[mi][ni][1] + by);
                *(float2*)&g_Y[(size_t)row0 * 896 + col] = o;
            }
            if (row0 + 8 < n) {
                float2 o = make_float2(acc[mi][ni][2] + bx, acc[mi][ni][3] + by);
                *(float2*)&g_Y[(size_t)(row0 + 8) * 896 + col] = o;
            }
        }
    }
}

// ---------------- elementwise: inner levels ----------------
__global__ void inner_elem_kernel(const float* __restrict__ cprev,
                                  float* __restrict__ out_h, float* __restrict__ out_c, int n) {
    int j = blockIdx.x;
    if (j >= n) return;
    int r = threadIdx.x;
    const float* Yr = g_Y + (size_t)j * 896;
    float iv = Yr[r], ov = Yr[128 + r], uv = Yr[256 + r];
    float c = sigf(iv) * tanhf(uv);
#pragma unroll
    for (int a = 0; a < 4; a++)
        c += sigf(Yr[384 + a * 128 + r]) * cprev[(size_t)(4 * j + a) * 128 + r];
    float h = sigf(ov) * tanhf(c);
    out_h[(size_t)j * 128 + r] = h;
    out_c[(size_t)j * 128 + r] = c;
}

// ---------------- launch ----------------
extern "C" void kernel_launch(void* const* d_in, const int* in_sizes, int n_in,
                              void* d_out, int out_size) {
    const float* emb    = (const float*)d_in[0];
    const float* W_iou  = (const float*)d_in[1];
    const float* b_iou  = (const float*)d_in[2];
    const float* U_iou  = (const float*)d_in[3];
    const float* b_uiou = (const float*)d_in[4];
    const float* W_f    = (const float*)d_in[5];
    const float* b_wf   = (const float*)d_in[6];
    const float* U_f    = (const float*)d_in[7];
    const float* b_uf   = (const float*)d_in[8];
    const float* h0     = (const float*)d_in[9];
    const float* c0     = (const float*)d_in[10];

    float* out_h = (float*)d_out;
    float* out_c = out_h + (size_t)NN * 128;

    cudaFuncSetAttribute(leaf_fused, cudaFuncAttributeMaxDynamicSharedMemorySize, 27648 * 4);
    cudaFuncSetAttribute(gemm_tc,    cudaFuncAttributeMaxDynamicSharedMemorySize, 18432 * 4);

    prep_M_kernel<<<512, 256>>>(W_iou, U_iou, b_iou, b_uiou, W_f, U_f, b_wf, b_uf);
    prep_const_kernel<<<7, 128>>>(U_iou, b_iou, b_uiou, U_f, b_uf, h0, b_wf);

    const int lev_n[9] = {65536, 16384, 4096, 1024, 256, 64, 16, 4, 1};
    int offs[10];
    offs[0] = 0;
    for (int i = 0; i < 9; i++) offs[i + 1] = offs[i] + lev_n[i];

    // leaf level: persistent fused kernel, 296 CTAs = 2 per SM
    leaf_fused<<<dim3(4, 74), 256, 27648 * 4>>>(emb, c0, out_h, out_c);

    // inner levels 7..0 (C=896, K=640)
    for (int i = 1; i < 9; i++) {
        int n = lev_n[i];
        const float* X  = emb   + (size_t)offs[i]     * 128;
        const float* Hp = out_h + (size_t)offs[i - 1] * 128;
        const float* Cp = out_c + (size_t)offs[i - 1] * 128;
        gemm_tc<<<dim3(7, (n + 127) / 128), 256, 18432 * 4>>>(X, Hp, n);
        inner_elem_kernel<<<n, 128>>>(Cp, out_h + (size_t)offs[i] * 128,
                                      out_c + (size_t)offs[i] * 128, n);
    }
}

// round 12
// speedup vs baseline: 1.6796x; 1.3986x over previous
#include <cuda_runtime.h>
#include <cuda_fp16.h>
#include <math.h>
#include <stdint.h>

// Tree-LSTM, 4-ary, depth 8. E=H=128, A=4. N_NODES=87381, leaves=65536.
// R12: fp16 HMMA m16n8k16 + ldmatrix + K-chunk 64 (fixes R11's leaf-B load bug:
// resident B is 128x128 halves -> 2048 cp.async iterations, not 1024).

#define NN     87381
#define NLEAF  65536

__device__ float  g_Y[(size_t)16384 * 896];
__device__ __half g_Mh[896 * 640];
__device__ float  g_bias[896];
__device__ __half g_Mleaf[512 * 128];          // PERMUTED col = h*4+gate
__device__ float  g_bleaf[512];                // PERMUTED
__device__ float  g_cuf[512];
__device__ __half g_emb16[(size_t)NN * 128];
__device__ __half g_h16[(size_t)NN * 128];

__device__ __forceinline__ float sigf(float x) { return 1.0f / (1.0f + expf(-x)); }
__device__ __forceinline__ void cp16(uint32_t dst, const void* src, uint32_t srcsz) {
    asm volatile("cp.async.ca.shared.global [%0], [%1], 16, %2;"
                 :: "r"(dst), "l"(src), "r"(srcsz));
}
#define CP_COMMIT() asm volatile("cp.async.commit_group;" ::: "memory")
#define CP_WAIT(N)  asm volatile("cp.async.wait_group %0;" :: "n"(N) : "memory")

__device__ __forceinline__ void ldm_x4(uint32_t* r, uint32_t addr) {
    asm volatile("ldmatrix.sync.aligned.m8n8.x4.shared.b16 {%0,%1,%2,%3}, [%4];"
                 : "=r"(r[0]), "=r"(r[1]), "=r"(r[2]), "=r"(r[3]) : "r"(addr));
}
__device__ __forceinline__ void ldm_x2(uint32_t* r, uint32_t addr) {
    asm volatile("ldmatrix.sync.aligned.m8n8.x2.shared.b16 {%0,%1}, [%2];"
                 : "=r"(r[0]), "=r"(r[1]) : "r"(addr));
}
__device__ __forceinline__ void mma16(float* c, const uint32_t* a, const uint32_t* b) {
    asm volatile(
        "mma.sync.aligned.m16n8k16.row.col.f32.f16.f16.f32 "
        "{%0,%1,%2,%3}, {%4,%5,%6,%7}, {%8,%9}, {%0,%1,%2,%3};"
        : "+f"(c[0]), "+f"(c[1]), "+f"(c[2]), "+f"(c[3])
        : "r"(a[0]), "r"(a[1]), "r"(a[2]), "r"(a[3]), "r"(b[0]), "r"(b[1]));
}

// ---------------- prep ----------------
__global__ void prep_M_kernel(const float* __restrict__ W_iou, const float* __restrict__ U_iou,
                              const float* __restrict__ b_iou, const float* __restrict__ b_uiou,
                              const float* __restrict__ W_f,  const float* __restrict__ U_f,
                              const float* __restrict__ b_wf, const float* __restrict__ b_uf) {
    int stride = gridDim.x * blockDim.x;
    int idx = blockIdx.x * blockDim.x + threadIdx.x;
    for (int t = idx; t < 896 * 640; t += stride) {
        int c = t / 640, k = t - c * 640;
        float v;
        if (c < 384) v = (k < 128) ? W_iou[c * 128 + k] : U_iou[c * 512 + (k - 128)];
        else {
            int cc = c - 384;
            v = (k < 128) ? W_f[(cc & 127) * 128 + k] : U_f[cc * 512 + (k - 128)];
        }
        g_Mh[t] = __float2half_rn(v);
    }
    for (int t = idx; t < 512 * 128; t += stride) {
        int c = t >> 7, k = t & 127;
        int h = c >> 2, g = c & 3;
        float v = (g < 3) ? W_iou[(g * 128 + h) * 128 + k] : W_f[h * 128 + k];
        g_Mleaf[t] = __float2half_rn(v);
    }
    if (idx < 896)
        g_bias[idx] = (idx < 384) ? (b_iou[idx] + b_uiou[idx])
                                  : (b_wf[(idx - 384) & 127] + b_uf[idx - 384]);
}

__global__ void emb2h_kernel(const float* __restrict__ emb) {
    int stride = gridDim.x * blockDim.x;
    const int total = NN * 128 / 4;
    for (int i = blockIdx.x * blockDim.x + threadIdx.x; i < total; i += stride) {
        float4 v = ((const float4*)emb)[i];
        __half2 p0 = __floats2half2_rn(v.x, v.y);
        __half2 p1 = __floats2half2_rn(v.z, v.w);
        uint2 u;
        u.x = *(const unsigned*)&p0;
        u.y = *(const unsigned*)&p1;
        ((uint2*)g_emb16)[i] = u;
    }
}

__global__ void prep_const_kernel(const float* __restrict__ U_iou, const float* __restrict__ b_iou,
                                  const float* __restrict__ b_uiou, const float* __restrict__ U_f,
                                  const float* __restrict__ b_uf, const float* __restrict__ h0,
                                  const float* __restrict__ b_wf) {
    int c = blockIdx.x * blockDim.x + threadIdx.x;
    if (c < 384) {
        int g = c >> 7, h = c & 127;
        float s = b_iou[c] + b_uiou[c];
        for (int k = 0; k < 512; k++) s += U_iou[c * 512 + k] * h0[k];
        g_bleaf[h * 4 + g] = s;
    } else if (c < 896) {
        int cc = c - 384;
        float s = b_uf[cc];
        for (int k = 0; k < 512; k++) s += U_f[cc * 512 + k] * h0[k];
        g_cuf[cc] = s;
        if (cc < 128) g_bleaf[cc * 4 + 3] = b_wf[cc];
    }
}

// ---------------- persistent fused leaf (fp16 mainloop, fp32 gates) ----------------
// smem halves: A[2][128][72] 0..18432 ; B[128][136] 18432..35840 ; fp32 consts at byte 71680.
// Epilogue buffer = A stage 1 (bytes 18432..36864, 128x36 fp32).
__global__ void __launch_bounds__(256, 2)
leaf_fused(const float* __restrict__ c0,
           float* __restrict__ out_h, float* __restrict__ out_c) {
    extern __shared__ __half smh[];
    uint32_t sbase = (uint32_t)__cvta_generic_to_shared(smh);
    const int BH = 18432;
    float* c0s  = (float*)((char*)smh + 71680);
    float* cufs = c0s + 512;
    float* bls  = cufs + 512;

    int tid = threadIdx.x, wid = tid >> 5, lane = tid & 31;
    int gid = lane >> 2, tig = lane & 3;
    int wr = wid >> 2, wc = wid & 3;
    int colBase = blockIdx.x * 128;
    int hgBase  = blockIdx.x * 32;

    int arow = (lane & 7) + ((lane >> 3) & 1) * 8;
    int ak   = (lane >> 4) * 8;
    int bl   = lane & 15;
    int brow = bl & 7;
    int bk   = ((bl >> 3) & 1) * 8;

    // resident B: 128 cols x 128 K halves (FIX: 2048 iterations, 16B each)
#pragma unroll 8
    for (int it = tid; it < 2048; it += 256) {
        int r = it >> 4, q = (it & 15) * 8;
        cp16(sbase + ((BH + r * 136 + q) << 1),
             g_Mleaf + (size_t)(colBase + r) * 128 + q, 16);
    }
    if (tid < 128) {
        cp16((uint32_t)__cvta_generic_to_shared(c0s)  + tid * 16, c0      + tid * 4, 16);
        cp16((uint32_t)__cvta_generic_to_shared(cufs) + tid * 16, g_cuf   + tid * 4, 16);
        cp16((uint32_t)__cvta_generic_to_shared(bls)  + tid * 16, g_bleaf + tid * 4, 16);
    }
    CP_COMMIT();

    auto loadA = [&](int rt, int kc, int st) {
        const __half* src = g_emb16 + (size_t)rt * 128 * 128 + kc * 64;
#pragma unroll
        for (int it = tid; it < 1024; it += 256) {
            int r = it >> 3, q = (it & 7) * 8;
            cp16(sbase + ((st * 9216 + r * 72 + q) << 1), src + (size_t)r * 128 + q, 16);
        }
    };

    loadA(blockIdx.y, 0, 0);
    CP_COMMIT();

    for (int rt = blockIdx.y; rt < 512; rt += 74) {
        loadA(rt, 1, 1);
        CP_COMMIT();

        float acc[4][4][4];
#pragma unroll
        for (int mi = 0; mi < 4; mi++)
#pragma unroll
            for (int ni = 0; ni < 4; ni++)
#pragma unroll
                for (int q = 0; q < 4; q++) acc[mi][ni][q] = 0.f;

#pragma unroll
        for (int kc = 0; kc < 2; kc++) {
            CP_WAIT(1);
            __syncthreads();
#pragma unroll
            for (int ks = 0; ks < 64; ks += 16) {
                uint32_t a[4][4], b[4][2];
#pragma unroll
                for (int mi = 0; mi < 4; mi++)
                    ldm_x4(a[mi], sbase + ((kc * 9216 +
                        (wr * 64 + mi * 16 + arow) * 72 + ks + ak) << 1));
#pragma unroll
                for (int ni = 0; ni < 4; ni++)
                    ldm_x2(b[ni], sbase + ((BH +
                        (wc * 32 + ni * 8 + brow) * 136 + kc * 64 + ks + bk) << 1));
#pragma unroll
                for (int mi = 0; mi < 4; mi++)
#pragma unroll
                    for (int ni = 0; ni < 4; ni++)
                        mma16(acc[mi][ni], a[mi], b[ni]);
            }
            __syncthreads();
            if (kc == 0) {
                int nrt = rt + 74; if (nrt >= 512) nrt = 0;
                loadA(nrt, 0, 0);
                CP_COMMIT();
            }
        }

        // epilogue: 4 column quarters via A stage 1 (bytes 18432.., 128x36 fp32)
        float (*Ysq)[36] = (float(*)[36])((char*)smh + 18432);
        int rowBaseG = rt * 128;
        int row = tid >> 1, hq = (tid & 1) * 4;
#pragma unroll
        for (int wq = 0; wq < 4; wq++) {
            if (wc == wq) {
#pragma unroll
                for (int mi = 0; mi < 4; mi++) {
                    int r0 = wr * 64 + mi * 16 + gid;
#pragma unroll
                    for (int ni = 0; ni < 4; ni++) {
                        int col = ni * 8 + tig * 2;
                        float bx = bls[colBase + wq * 32 + col];
                        float by = bls[colBase + wq * 32 + col + 1];
                        Ysq[r0][col]         = acc[mi][ni][0] + bx;
                        Ysq[r0][col + 1]     = acc[mi][ni][1] + by;
                        Ysq[r0 + 8][col]     = acc[mi][ni][2] + bx;
                        Ysq[r0 + 8][col + 1] = acc[mi][ni][3] + by;
                    }
                }
            }
            __syncthreads();
            float hb[4], cb[4];
#pragma unroll
            for (int j = 0; j < 4; j++) {
                int hl = hq + j;
                float4 v = *(const float4*)&Ysq[row][hl * 4];   // i, o, u, wf
                int hg = hgBase + wq * 8 + hl;
                float cc = sigf(v.x) * tanhf(v.z);
#pragma unroll
                for (int a = 0; a < 4; a++)
                    cc += sigf(v.w + cufs[a * 128 + hg]) * c0s[a * 128 + hg];
                hb[j] = sigf(v.y) * tanhf(cc);
                cb[j] = cc;
            }
            size_t ob = (size_t)(rowBaseG + row) * 128 + hgBase + wq * 8 + hq;
            *(float4*)(out_h + ob) = make_float4(hb[0], hb[1], hb[2], hb[3]);
            *(float4*)(out_c + ob) = make_float4(cb[0], cb[1], cb[2], cb[3]);
            __half2 p0 = __floats2half2_rn(hb[0], hb[1]);
            __half2 p1 = __floats2half2_rn(hb[2], hb[3]);
            uint2 u; u.x = *(const unsigned*)&p0; u.y = *(const unsigned*)&p1;
            *(uint2*)(g_h16 + ob) = u;
            __syncthreads();
        }
    }
}

// ---------------- inner pipelined GEMM (fp16): offsets into g_emb16/g_h16 ----------------
// smem halves: A[2][128][72] 0..18432, B[2][128][72] 18432..36864 (73.7KB)
__global__ void __launch_bounds__(256, 2)
gemm_tc(int embOff, int hOff, int n) {
    extern __shared__ __half smh[];
    uint32_t sbase = (uint32_t)__cvta_generic_to_shared(smh);
    const int BH = 18432;
    const __half* X16  = g_emb16 + (size_t)embOff * 128;
    const __half* Hp16 = g_h16   + (size_t)hOff   * 128;

    int tid = threadIdx.x, wid = tid >> 5, lane = tid & 31;
    int gid = lane >> 2, tig = lane & 3;
    int wr = wid >> 2, wc = wid & 3;
    int rowBase = blockIdx.y * 128, colBase = blockIdx.x * 128;

    int arow = (lane & 7) + ((lane >> 3) & 1) * 8;
    int ak   = (lane >> 4) * 8;
    int bl   = lane & 15;
    int brow = bl & 7;
    int bk   = ((bl >> 3) & 1) * 8;

    float acc[4][4][4];
#pragma unroll
    for (int mi = 0; mi < 4; mi++)
#pragma unroll
        for (int ni = 0; ni < 4; ni++)
#pragma unroll
            for (int q = 0; q < 4; q++) acc[mi][ni][q] = 0.f;

    auto loadAB = [&](int kc, int st) {
        int k0 = kc * 64;
        const __half* base; int pitch, koff;
        if (k0 < 128) { base = X16;  pitch = 128; koff = k0; }
        else          { base = Hp16; pitch = 512; koff = k0 - 128; }
#pragma unroll
        for (int it = tid; it < 1024; it += 256) {
            int r = it >> 3, q = (it & 7) * 8;
            int row = rowBase + r;
            cp16(sbase + ((st * 9216 + r * 72 + q) << 1),
                 base + (size_t)row * pitch + koff + q, (row < n) ? 16u : 0u);
        }
#pragma unroll
        for (int it = tid; it < 1024; it += 256) {
            int r = it >> 3, q = (it & 7) * 8;
            cp16(sbase + ((BH + st * 9216 + r * 72 + q) << 1),
                 g_Mh + (size_t)(colBase + r) * 640 + k0 + q, 16);
        }
    };

    loadAB(0, 0);
    CP_COMMIT();

    for (int kc = 0; kc < 10; kc++) {
        int cur = kc & 1;
        if (kc < 9) {
            loadAB(kc + 1, cur ^ 1);
            CP_COMMIT();
            CP_WAIT(1);
        } else {
            CP_WAIT(0);
        }
        __syncthreads();
#pragma unroll
        for (int ks = 0; ks < 64; ks += 16) {
            uint32_t a[4][4], b[4][2];
#pragma unroll
            for (int mi = 0; mi < 4; mi++)
                ldm_x4(a[mi], sbase + ((cur * 9216 +
                    (wr * 64 + mi * 16 + arow) * 72 + ks + ak) << 1));
#pragma unroll
            for (int ni = 0; ni < 4; ni++)
                ldm_x2(b[ni], sbase + ((BH + cur * 9216 +
                    (wc * 32 + ni * 8 + brow) * 72 + ks + bk) << 1));
#pragma unroll
            for (int mi = 0; mi < 4; mi++)
#pragma unroll
                for (int ni = 0; ni < 4; ni++)
                    mma16(acc[mi][ni], a[mi], b[ni]);
        }
        __syncthreads();
    }

#pragma unroll
    for (int mi = 0; mi < 4; mi++) {
        int row0 = rowBase + wr * 64 + mi * 16 + gid;
#pragma unroll
        for (int ni = 0; ni < 4; ni++) {
            int col = colBase + wc * 32 + ni * 8 + tig * 2;
            float bx = g_bias[col], by = g_bias[col + 1];
            if (row0 < n) {
                float2 o = make_float2(acc[mi][ni][0] + bx, acc[mi][ni][1] + by);
                *(float2*)&g_Y[(size_t)row0 * 896 + col] = o;
            }
            if (row0 + 8 < n) {
                float2 o = make_float2(acc[mi][ni][2] + bx, acc[mi][ni][3] + by);
                *(float2*)&g_Y[(size_t)(row0 + 8) * 896 + col] = o;
            }
        }
    }
}

// ---------------- elementwise: inner levels (also emits fp16 h into g_h16) ------------
__global__ void inner_elem_kernel(const float* __restrict__ cprev,
                                  float* __restrict__ out_h, float* __restrict__ out_c,
                                  int hOff, int n) {
    int j = blockIdx.x;
    if (j >= n) return;
    int r = threadIdx.x;
    const float* Yr = g_Y + (size_t)j * 896;
    float iv = Yr[r], ov = Yr[128 + r], uv = Yr[256 + r];
    float c = sigf(iv) * tanhf(uv);
#pragma unroll
    for (int a = 0; a < 4; a++)
        c += sigf(Yr[384 + a * 128 + r]) * cprev[(size_t)(4 * j + a) * 128 + r];
    float h = sigf(ov) * tanhf(c);
    out_h[(size_t)j * 128 + r] = h;
    out_c[(size_t)j * 128 + r] = c;
    g_h16[(size_t)(hOff + j) * 128 + r] = __float2half_rn(h);
}

// ---------------- launch ----------------
extern "C" void kernel_launch(void* const* d_in, const int* in_sizes, int n_in,
                              void* d_out, int out_size) {
    const float* emb    = (const float*)d_in[0];
    const float* W_iou  = (const float*)d_in[1];
    const float* b_iou  = (const float*)d_in[2];
    const float* U_iou  = (const float*)d_in[3];
    const float* b_uiou = (const float*)d_in[4];
    const float* W_f    = (const float*)d_in[5];
    const float* b_wf   = (const float*)d_in[6];
    const float* U_f    = (const float*)d_in[7];
    const float* b_uf   = (const float*)d_in[8];
    const float* h0     = (const float*)d_in[9];
    const float* c0     = (const float*)d_in[10];

    float* out_h = (float*)d_out;
    float* out_c = out_h + (size_t)NN * 128;

    cudaFuncSetAttribute(leaf_fused, cudaFuncAttributeMaxDynamicSharedMemorySize, 77824);
    cudaFuncSetAttribute(gemm_tc,    cudaFuncAttributeMaxDynamicSharedMemorySize, 73728);

    prep_M_kernel<<<512, 256>>>(W_iou, U_iou, b_iou, b_uiou, W_f, U_f, b_wf, b_uf);
    emb2h_kernel<<<512, 256>>>(emb);
    prep_const_kernel<<<7, 128>>>(U_iou, b_iou, b_uiou, U_f, b_uf, h0, b_wf);

    const int lev_n[9] = {65536, 16384, 4096, 1024, 256, 64, 16, 4, 1};
    int offs[10];
    offs[0] = 0;
    for (int i = 0; i < 9; i++) offs[i + 1] = offs[i] + lev_n[i];

    // leaf level: persistent fused kernel (also fills g_h16[0:65536])
    leaf_fused<<<dim3(4, 74), 256, 77824>>>(c0, out_h, out_c);

    // inner levels 7..0
    for (int i = 1; i < 9; i++) {
        int n = lev_n[i];
        const float* Cp = out_c + (size_t)offs[i - 1] * 128;
        gemm_tc<<<dim3(7, (n + 127) / 128), 256, 73728>>>(offs[i], offs[i - 1], n);
        inner_elem_kernel<<<n, 128>>>(Cp, out_h + (size_t)offs[i] * 128,
                                      out_c + (size_t)offs[i] * 128, offs[i], n);
    }
}

// round 13
// speedup vs baseline: 1.9625x; 1.1685x over previous
#include <cuda_runtime.h>
#include <cuda_fp16.h>
#include <math.h>
#include <stdint.h>

// Tree-LSTM, 4-ary, depth 8. E=H=128, A=4. N_NODES=87381, leaves=65536.
// R13: R12 + fast transcendentals (__expf/__fdividef) in all gate math.
// fp16 HMMA m16n8k16 + ldmatrix + K-chunk 64; leaf persistent+fused.

#define NN     87381
#define NLEAF  65536

__device__ float  g_Y[(size_t)16384 * 896];
__device__ __half g_Mh[896 * 640];
__device__ float  g_bias[896];
__device__ __half g_Mleaf[512 * 128];          // PERMUTED col = h*4+gate
__device__ float  g_bleaf[512];                // PERMUTED
__device__ float  g_cuf[512];
__device__ __half g_emb16[(size_t)NN * 128];
__device__ __half g_h16[(size_t)NN * 128];

__device__ __forceinline__ float sigf(float x) {
    return __fdividef(1.f, 1.f + __expf(-x));
}
__device__ __forceinline__ float tanh_fast(float x) {
    return 1.f - __fdividef(2.f, __expf(2.f * x) + 1.f);
}
__device__ __forceinline__ void cp16(uint32_t dst, const void* src, uint32_t srcsz) {
    asm volatile("cp.async.ca.shared.global [%0], [%1], 16, %2;"
                 :: "r"(dst), "l"(src), "r"(srcsz));
}
#define CP_COMMIT() asm volatile("cp.async.commit_group;" ::: "memory")
#define CP_WAIT(N)  asm volatile("cp.async.wait_group %0;" :: "n"(N) : "memory")

__device__ __forceinline__ void ldm_x4(uint32_t* r, uint32_t addr) {
    asm volatile("ldmatrix.sync.aligned.m8n8.x4.shared.b16 {%0,%1,%2,%3}, [%4];"
                 : "=r"(r[0]), "=r"(r[1]), "=r"(r[2]), "=r"(r[3]) : "r"(addr));
}
__device__ __forceinline__ void ldm_x2(uint32_t* r, uint32_t addr) {
    asm volatile("ldmatrix.sync.aligned.m8n8.x2.shared.b16 {%0,%1}, [%2];"
                 : "=r"(r[0]), "=r"(r[1]) : "r"(addr));
}
__device__ __forceinline__ void mma16(float* c, const uint32_t* a, const uint32_t* b) {
    asm volatile(
        "mma.sync.aligned.m16n8k16.row.col.f32.f16.f16.f32 "
        "{%0,%1,%2,%3}, {%4,%5,%6,%7}, {%8,%9}, {%0,%1,%2,%3};"
        : "+f"(c[0]), "+f"(c[1]), "+f"(c[2]), "+f"(c[3])
        : "r"(a[0]), "r"(a[1]), "r"(a[2]), "r"(a[3]), "r"(b[0]), "r"(b[1]));
}

// ---------------- prep ----------------
__global__ void prep_M_kernel(const float* __restrict__ W_iou, const float* __restrict__ U_iou,
                              const float* __restrict__ b_iou, const float* __restrict__ b_uiou,
                              const float* __restrict__ W_f,  const float* __restrict__ U_f,
                              const float* __restrict__ b_wf, const float* __restrict__ b_uf) {
    int stride = gridDim.x * blockDim.x;
    int idx = blockIdx.x * blockDim.x + threadIdx.x;
    for (int t = idx; t < 896 * 640; t += stride) {
        int c = t / 640, k = t - c * 640;
        float v;
        if (c < 384) v = (k < 128) ? W_iou[c * 128 + k] : U_iou[c * 512 + (k - 128)];
        else {
            int cc = c - 384;
            v = (k < 128) ? W_f[(cc & 127) * 128 + k] : U_f[cc * 512 + (k - 128)];
        }
        g_Mh[t] = __float2half_rn(v);
    }
    for (int t = idx; t < 512 * 128; t += stride) {
        int c = t >> 7, k = t & 127;
        int h = c >> 2, g = c & 3;
        float v = (g < 3) ? W_iou[(g * 128 + h) * 128 + k] : W_f[h * 128 + k];
        g_Mleaf[t] = __float2half_rn(v);
    }
    if (idx < 896)
        g_bias[idx] = (idx < 384) ? (b_iou[idx] + b_uiou[idx])
                                  : (b_wf[(idx - 384) & 127] + b_uf[idx - 384]);
}

__global__ void emb2h_kernel(const float* __restrict__ emb) {
    int stride = gridDim.x * blockDim.x;
    const int total = NN * 128 / 4;
    for (int i = blockIdx.x * blockDim.x + threadIdx.x; i < total; i += stride) {
        float4 v = ((const float4*)emb)[i];
        __half2 p0 = __floats2half2_rn(v.x, v.y);
        __half2 p1 = __floats2half2_rn(v.z, v.w);
        uint2 u;
        u.x = *(const unsigned*)&p0;
        u.y = *(const unsigned*)&p1;
        ((uint2*)g_emb16)[i] = u;
    }
}

__global__ void prep_const_kernel(const float* __restrict__ U_iou, const float* __restrict__ b_iou,
                                  const float* __restrict__ b_uiou, const float* __restrict__ U_f,
                                  const float* __restrict__ b_uf, const float* __restrict__ h0,
                                  const float* __restrict__ b_wf) {
    int c = blockIdx.x * blockDim.x + threadIdx.x;
    if (c < 384) {
        int g = c >> 7, h = c & 127;
        float s = b_iou[c] + b_uiou[c];
        for (int k = 0; k < 512; k++) s += U_iou[c * 512 + k] * h0[k];
        g_bleaf[h * 4 + g] = s;
    } else if (c < 896) {
        int cc = c - 384;
        float s = b_uf[cc];
        for (int k = 0; k < 512; k++) s += U_f[cc * 512 + k] * h0[k];
        g_cuf[cc] = s;
        if (cc < 128) g_bleaf[cc * 4 + 3] = b_wf[cc];
    }
}

// ---------------- persistent fused leaf (fp16 mainloop, fp32 gates) ----------------
// smem halves: A[2][128][72] 0..18432 ; B[128][136] 18432..35840 ; fp32 consts at byte 71680.
__global__ void __launch_bounds__(256, 2)
leaf_fused(const float* __restrict__ c0,
           float* __restrict__ out_h, float* __restrict__ out_c) {
    extern __shared__ __half smh[];
    uint32_t sbase = (uint32_t)__cvta_generic_to_shared(smh);
    const int BH = 18432;
    float* c0s  = (float*)((char*)smh + 71680);
    float* cufs = c0s + 512;
    float* bls  = cufs + 512;

    int tid = threadIdx.x, wid = tid >> 5, lane = tid & 31;
    int gid = lane >> 2, tig = lane & 3;
    int wr = wid >> 2, wc = wid & 3;
    int colBase = blockIdx.x * 128;
    int hgBase  = blockIdx.x * 32;

    int arow = (lane & 7) + ((lane >> 3) & 1) * 8;
    int ak   = (lane >> 4) * 8;
    int bl   = lane & 15;
    int brow = bl & 7;
    int bk   = ((bl >> 3) & 1) * 8;

    // resident B: 128 cols x 128 K halves
#pragma unroll 8
    for (int it = tid; it < 2048; it += 256) {
        int r = it >> 4, q = (it & 15) * 8;
        cp16(sbase + ((BH + r * 136 + q) << 1),
             g_Mleaf + (size_t)(colBase + r) * 128 + q, 16);
    }
    if (tid < 128) {
        cp16((uint32_t)__cvta_generic_to_shared(c0s)  + tid * 16, c0      + tid * 4, 16);
        cp16((uint32_t)__cvta_generic_to_shared(cufs) + tid * 16, g_cuf   + tid * 4, 16);
        cp16((uint32_t)__cvta_generic_to_shared(bls)  + tid * 16, g_bleaf + tid * 4, 16);
    }
    CP_COMMIT();

    auto loadA = [&](int rt, int kc, int st) {
        const __half* src = g_emb16 + (size_t)rt * 128 * 128 + kc * 64;
#pragma unroll
        for (int it = tid; it < 1024; it += 256) {
            int r = it >> 3, q = (it & 7) * 8;
            cp16(sbase + ((st * 9216 + r * 72 + q) << 1), src + (size_t)r * 128 + q, 16);
        }
    };

    loadA(blockIdx.y, 0, 0);
    CP_COMMIT();

    for (int rt = blockIdx.y; rt < 512; rt += 74) {
        loadA(rt, 1, 1);
        CP_COMMIT();

        float acc[4][4][4];
#pragma unroll
        for (int mi = 0; mi < 4; mi++)
#pragma unroll
            for (int ni = 0; ni < 4; ni++)
#pragma unroll
                for (int q = 0; q < 4; q++) acc[mi][ni][q] = 0.f;

#pragma unroll
        for (int kc = 0; kc < 2; kc++) {
            CP_WAIT(1);
            __syncthreads();
#pragma unroll
            for (int ks = 0; ks < 64; ks += 16) {
                uint32_t a[4][4], b[4][2];
#pragma unroll
                for (int mi = 0; mi < 4; mi++)
                    ldm_x4(a[mi], sbase + ((kc * 9216 +
                        (wr * 64 + mi * 16 + arow) * 72 + ks + ak) << 1));
#pragma unroll
                for (int ni = 0; ni < 4; ni++)
                    ldm_x2(b[ni], sbase + ((BH +
                        (wc * 32 + ni * 8 + brow) * 136 + kc * 64 + ks + bk) << 1));
#pragma unroll
                for (int mi = 0; mi < 4; mi++)
#pragma unroll
                    for (int ni = 0; ni < 4; ni++)
                        mma16(acc[mi][ni], a[mi], b[ni]);
            }
            __syncthreads();
            if (kc == 0) {
                int nrt = rt + 74; if (nrt >= 512) nrt = 0;
                loadA(nrt, 0, 0);
                CP_COMMIT();
            }
        }

        // epilogue: 4 column quarters via A stage 1 (bytes 18432.., 128x36 fp32)
        float (*Ysq)[36] = (float(*)[36])((char*)smh + 18432);
        int rowBaseG = rt * 128;
        int row = tid >> 1, hq = (tid & 1) * 4;
#pragma unroll
        for (int wq = 0; wq < 4; wq++) {
            if (wc == wq) {
#pragma unroll
                for (int mi = 0; mi < 4; mi++) {
                    int r0 = wr * 64 + mi * 16 + gid;
#pragma unroll
                    for (int ni = 0; ni < 4; ni++) {
                        int col = ni * 8 + tig * 2;
                        float bx = bls[colBase + wq * 32 + col];
                        float by = bls[colBase + wq * 32 + col + 1];
                        Ysq[r0][col]         = acc[mi][ni][0] + bx;
                        Ysq[r0][col + 1]     = acc[mi][ni][1] + by;
                        Ysq[r0 + 8][col]     = acc[mi][ni][2] + bx;
                        Ysq[r0 + 8][col + 1] = acc[mi][ni][3] + by;
                    }
                }
            }
            __syncthreads();
            float hb[4], cb[4];
#pragma unroll
            for (int j = 0; j < 4; j++) {
                int hl = hq + j;
                float4 v = *(const float4*)&Ysq[row][hl * 4];   // i, o, u, wf
                int hg = hgBase + wq * 8 + hl;
                float cc = sigf(v.x) * tanh_fast(v.z);
#pragma unroll
                for (int a = 0; a < 4; a++)
                    cc += sigf(v.w + cufs[a * 128 + hg]) * c0s[a * 128 + hg];
                hb[j] = sigf(v.y) * tanh_fast(cc);
                cb[j] = cc;
            }
            size_t ob = (size_t)(rowBaseG + row) * 128 + hgBase + wq * 8 + hq;
            *(float4*)(out_h + ob) = make_float4(hb[0], hb[1], hb[2], hb[3]);
            *(float4*)(out_c + ob) = make_float4(cb[0], cb[1], cb[2], cb[3]);
            __half2 p0 = __floats2half2_rn(hb[0], hb[1]);
            __half2 p1 = __floats2half2_rn(hb[2], hb[3]);
            uint2 u; u.x = *(const unsigned*)&p0; u.y = *(const unsigned*)&p1;
            *(uint2*)(g_h16 + ob) = u;
            __syncthreads();
        }
    }
}

// ---------------- inner pipelined GEMM (fp16): offsets into g_emb16/g_h16 ----------------
__global__ void __launch_bounds__(256, 2)
gemm_tc(int embOff, int hOff, int n) {
    extern __shared__ __half smh[];
    uint32_t sbase = (uint32_t)__cvta_generic_to_shared(smh);
    const int BH = 18432;
    const __half* X16  = g_emb16 + (size_t)embOff * 128;
    const __half* Hp16 = g_h16   + (size_t)hOff   * 128;

    int tid = threadIdx.x, wid = tid >> 5, lane = tid & 31;
    int gid = lane >> 2, tig = lane & 3;
    int wr = wid >> 2, wc = wid & 3;
    int rowBase = blockIdx.y * 128, colBase = blockIdx.x * 128;

    int arow = (lane & 7) + ((lane >> 3) & 1) * 8;
    int ak   = (lane >> 4) * 8;
    int bl   = lane & 15;
    int brow = bl & 7;
    int bk   = ((bl >> 3) & 1) * 8;

    float acc[4][4][4];
#pragma unroll
    for (int mi = 0; mi < 4; mi++)
#pragma unroll
        for (int ni = 0; ni < 4; ni++)
#pragma unroll
            for (int q = 0; q < 4; q++) acc[mi][ni][q] = 0.f;

    auto loadAB = [&](int kc, int st) {
        int k0 = kc * 64;
        const __half* base; int pitch, koff;
        if (k0 < 128) { base = X16;  pitch = 128; koff = k0; }
        else          { base = Hp16; pitch = 512; koff = k0 - 128; }
#pragma unroll
        for (int it = tid; it < 1024; it += 256) {
            int r = it >> 3, q = (it & 7) * 8;
            int row = rowBase + r;
            cp16(sbase + ((st * 9216 + r * 72 + q) << 1),
                 base + (size_t)row * pitch + koff + q, (row < n) ? 16u : 0u);
        }
#pragma unroll
        for (int it = tid; it < 1024; it += 256) {
            int r = it >> 3, q = (it & 7) * 8;
            cp16(sbase + ((BH + st * 9216 + r * 72 + q) << 1),
                 g_Mh + (size_t)(colBase + r) * 640 + k0 + q, 16);
        }
    };

    loadAB(0, 0);
    CP_COMMIT();

    for (int kc = 0; kc < 10; kc++) {
        int cur = kc & 1;
        if (kc < 9) {
            loadAB(kc + 1, cur ^ 1);
            CP_COMMIT();
            CP_WAIT(1);
        } else {
            CP_WAIT(0);
        }
        __syncthreads();
#pragma unroll
        for (int ks = 0; ks < 64; ks += 16) {
            uint32_t a[4][4], b[4][2];
#pragma unroll
            for (int mi = 0; mi < 4; mi++)
                ldm_x4(a[mi], sbase + ((cur * 9216 +
                    (wr * 64 + mi * 16 + arow) * 72 + ks + ak) << 1));
#pragma unroll
            for (int ni = 0; ni < 4; ni++)
                ldm_x2(b[ni], sbase + ((BH + cur * 9216 +
                    (wc * 32 + ni * 8 + brow) * 72 + ks + bk) << 1));
#pragma unroll
            for (int mi = 0; mi < 4; mi++)
#pragma unroll
                for (int ni = 0; ni < 4; ni++)
                    mma16(acc[mi][ni], a[mi], b[ni]);
        }
        __syncthreads();
    }

#pragma unroll
    for (int mi = 0; mi < 4; mi++) {
        int row0 = rowBase + wr * 64 + mi * 16 + gid;
#pragma unroll
        for (int ni = 0; ni < 4; ni++) {
            int col = colBase + wc * 32 + ni * 8 + tig * 2;
            float bx = g_bias[col], by = g_bias[col + 1];
            if (row0 < n) {
                float2 o = make_float2(acc[mi][ni][0] + bx, acc[mi][ni][1] + by);
                *(float2*)&g_Y[(size_t)row0 * 896 + col] = o;
            }
            if (row0 + 8 < n) {
                float2 o = make_float2(acc[mi][ni][2] + bx, acc[mi][ni][3] + by);
                *(float2*)&g_Y[(size_t)(row0 + 8) * 896 + col] = o;
            }
        }
    }
}

// ---------------- elementwise: inner levels (also emits fp16 h into g_h16) ------------
__global__ void inner_elem_kernel(const float* __restrict__ cprev,
                                  float* __restrict__ out_h, float* __restrict__ out_c,
                                  int hOff, int n) {
    int j = blockIdx.x;
    if (j >= n) return;
    int r = threadIdx.x;
    const float* Yr = g_Y + (size_t)j * 896;
    float iv = Yr[r], ov = Yr[128 + r], uv = Yr[256 + r];
    float c = sigf(iv) * tanh_fast(uv);
#pragma unroll
    for (int a = 0; a < 4; a++)
        c += sigf(Yr[384 + a * 128 + r]) * cprev[(size_t)(4 * j + a) * 128 + r];
    float h = sigf(ov) * tanh_fast(c);
    out_h[(size_t)j * 128 + r] = h;
    out_c[(size_t)j * 128 + r] = c;
    g_h16[(size_t)(hOff + j) * 128 + r] = __float2half_rn(h);
}

// ---------------- launch ----------------
extern "C" void kernel_launch(void* const* d_in, const int* in_sizes, int n_in,
                              void* d_out, int out_size) {
    const float* emb    = (const float*)d_in[0];
    const float* W_iou  = (const float*)d_in[1];
    const float* b_iou  = (const float*)d_in[2];
    const float* U_iou  = (const float*)d_in[3];
    const float* b_uiou = (const float*)d_in[4];
    const float* W_f    = (const float*)d_in[5];
    const float* b_wf   = (const float*)d_in[6];
    const float* U_f    = (const float*)d_in[7];
    const float* b_uf   = (const float*)d_in[8];
    const float* h0     = (const float*)d_in[9];
    const float* c0     = (const float*)d_in[10];

    float* out_h = (float*)d_out;
    float* out_c = out_h + (size_t)NN * 128;

    cudaFuncSetAttribute(leaf_fused, cudaFuncAttributeMaxDynamicSharedMemorySize, 77824);
    cudaFuncSetAttribute(gemm_tc,    cudaFuncAttributeMaxDynamicSharedMemorySize, 73728);

    prep_M_kernel<<<512, 256>>>(W_iou, U_iou, b_iou, b_uiou, W_f, U_f, b_wf, b_uf);
    emb2h_kernel<<<512, 256>>>(emb);
    prep_const_kernel<<<7, 128>>>(U_iou, b_iou, b_uiou, U_f, b_uf, h0, b_wf);

    const int lev_n[9] = {65536, 16384, 4096, 1024, 256, 64, 16, 4, 1};
    int offs[10];
    offs[0] = 0;
    for (int i = 0; i < 9; i++) offs[i + 1] = offs[i] + lev_n[i];

    // leaf level: persistent fused kernel (also fills g_h16[0:65536])
    leaf_fused<<<dim3(4, 74), 256, 77824>>>(c0, out_h, out_c);

    // inner levels 7..0
    for (int i = 1; i < 9; i++) {
        int n = lev_n[i];
        const float* Cp = out_c + (size_t)offs[i - 1] * 128;
        gemm_tc<<<dim3(7, (n + 127) / 128), 256, 73728>>>(offs[i], offs[i - 1], n);
        inner_elem_kernel<<<n, 128>>>(Cp, out_h + (size_t)offs[i] * 128,
                                      out_c + (size_t)offs[i] * 128, offs[i], n);
    }
}

// round 14
// speedup vs baseline: 2.2003x; 1.1212x over previous
#include <cuda_runtime.h>
#include <cuda_fp16.h>
#include <math.h>
#include <stdint.h>

// Tree-LSTM, 4-ary, depth 8. E=H=128, A=4. N_NODES=87381, leaves=65536.
// R14: (a) warp-parallel prep_const; (b) inner levels fully fused: gate-interleaved
// weight layout cp=h*7+g, N-tile 112 (16 H/CTA), epilogue through reused A/B smem.
// g_Y and inner_elem deleted. Leaf kernel identical to R13.

#define NN     87381
#define NLEAF  65536

__device__ __half g_Mh[896 * 640];             // inner weight, PERMUTED cp = h*7+g
__device__ float  g_bias[896];                 // inner bias, PERMUTED
__device__ __half g_Mleaf[512 * 128];          // leaf weight, PERMUTED col = h*4+gate
__device__ float  g_bleaf[512];                // leaf bias, PERMUTED
__device__ float  g_cuf[512];
__device__ __half g_emb16[(size_t)NN * 128];
__device__ __half g_h16[(size_t)NN * 128];

__device__ __forceinline__ float sigf(float x) {
    return __fdividef(1.f, 1.f + __expf(-x));
}
__device__ __forceinline__ float tanh_fast(float x) {
    return 1.f - __fdividef(2.f, __expf(2.f * x) + 1.f);
}
__device__ __forceinline__ void cp16(uint32_t dst, const void* src, uint32_t srcsz) {
    asm volatile("cp.async.ca.shared.global [%0], [%1], 16, %2;"
                 :: "r"(dst), "l"(src), "r"(srcsz));
}
#define CP_COMMIT() asm volatile("cp.async.commit_group;" ::: "memory")
#define CP_WAIT(N)  asm volatile("cp.async.wait_group %0;" :: "n"(N) : "memory")

__device__ __forceinline__ void ldm_x4(uint32_t* r, uint32_t addr) {
    asm volatile("ldmatrix.sync.aligned.m8n8.x4.shared.b16 {%0,%1,%2,%3}, [%4];"
                 : "=r"(r[0]), "=r"(r[1]), "=r"(r[2]), "=r"(r[3]) : "r"(addr));
}
__device__ __forceinline__ void ldm_x2(uint32_t* r, uint32_t addr) {
    asm volatile("ldmatrix.sync.aligned.m8n8.x2.shared.b16 {%0,%1}, [%2];"
                 : "=r"(r[0]), "=r"(r[1]) : "r"(addr));
}
__device__ __forceinline__ void mma16(float* c, const uint32_t* a, const uint32_t* b) {
    asm volatile(
        "mma.sync.aligned.m16n8k16.row.col.f32.f16.f16.f32 "
        "{%0,%1,%2,%3}, {%4,%5,%6,%7}, {%8,%9}, {%0,%1,%2,%3};"
        : "+f"(c[0]), "+f"(c[1]), "+f"(c[2]), "+f"(c[3])
        : "r"(a[0]), "r"(a[1]), "r"(a[2]), "r"(a[3]), "r"(b[0]), "r"(b[1]));
}

// ---------------- prep ----------------
__global__ void prep_M_kernel(const float* __restrict__ W_iou, const float* __restrict__ U_iou,
                              const float* __restrict__ b_iou, const float* __restrict__ b_uiou,
                              const float* __restrict__ W_f,  const float* __restrict__ U_f,
                              const float* __restrict__ b_wf, const float* __restrict__ b_uf) {
    int stride = gridDim.x * blockDim.x;
    int idx = blockIdx.x * blockDim.x + threadIdx.x;
    // inner weight, PERMUTED: cp = h*7+g ; g<3 -> iou row g*128+h ; g>=3 -> f row (g-3)*128+h
    for (int t = idx; t < 896 * 640; t += stride) {
        int cp = t / 640, k = t - cp * 640;
        int h = cp / 7, g = cp - h * 7;
        float v;
        if (g < 3) {
            int c = g * 128 + h;
            v = (k < 128) ? W_iou[c * 128 + k] : U_iou[c * 512 + (k - 128)];
        } else {
            int cc = (g - 3) * 128 + h;
            v = (k < 128) ? W_f[h * 128 + k] : U_f[cc * 512 + (k - 128)];
        }
        g_Mh[t] = __float2half_rn(v);
    }
    // leaf weight, PERMUTED: col c = h*4+g
    for (int t = idx; t < 512 * 128; t += stride) {
        int c = t >> 7, k = t & 127;
        int h = c >> 2, g = c & 3;
        float v = (g < 3) ? W_iou[(g * 128 + h) * 128 + k] : W_f[h * 128 + k];
        g_Mleaf[t] = __float2half_rn(v);
    }
    if (idx < 896) {
        int h = idx / 7, g = idx - h * 7;
        float v;
        if (g < 3) { int c = g * 128 + h; v = b_iou[c] + b_uiou[c]; }
        else       { int cc = (g - 3) * 128 + h; v = b_wf[h] + b_uf[cc]; }
        g_bias[idx] = v;
    }
}

__global__ void emb2h_kernel(const float* __restrict__ emb) {
    int stride = gridDim.x * blockDim.x;
    const int total = NN * 128 / 4;
    for (int i = blockIdx.x * blockDim.x + threadIdx.x; i < total; i += stride) {
        float4 v = ((const float4*)emb)[i];
        __half2 p0 = __floats2half2_rn(v.x, v.y);
        __half2 p1 = __floats2half2_rn(v.z, v.w);
        uint2 u;
        u.x = *(const unsigned*)&p0;
        u.y = *(const unsigned*)&p1;
        ((uint2*)g_emb16)[i] = u;
    }
}

// one warp per output row: lane-strided loads + shfl reduction
__global__ void prep_const_kernel(const float* __restrict__ U_iou, const float* __restrict__ b_iou,
                                  const float* __restrict__ b_uiou, const float* __restrict__ U_f,
                                  const float* __restrict__ b_uf, const float* __restrict__ h0,
                                  const float* __restrict__ b_wf) {
    int w = (blockIdx.x * blockDim.x + threadIdx.x) >> 5;
    int lane = threadIdx.x & 31;
    if (w >= 896) return;
    float s = 0.f;
    if (w < 384) {
        const float* row = U_iou + (size_t)w * 512;
        for (int k = lane; k < 512; k += 32) s += row[k] * h0[k];
    } else {
        const float* row = U_f + (size_t)(w - 384) * 512;
        for (int k = lane; k < 512; k += 32) s += row[k] * h0[k];
    }
#pragma unroll
    for (int o = 16; o; o >>= 1) s += __shfl_xor_sync(0xFFFFFFFFu, s, o);
    if (lane == 0) {
        if (w < 384) {
            int g = w >> 7, h = w & 127;
            g_bleaf[h * 4 + g] = s + b_iou[w] + b_uiou[w];
        } else {
            int cc = w - 384;
            g_cuf[cc] = s + b_uf[cc];
            if (cc < 128) g_bleaf[cc * 4 + 3] = b_wf[cc];
        }
    }
}

// ---------------- persistent fused leaf (identical to R13) ----------------
__global__ void __launch_bounds__(256, 2)
leaf_fused(const float* __restrict__ c0,
           float* __restrict__ out_h, float* __restrict__ out_c) {
    extern __shared__ __half smh[];
    uint32_t sbase = (uint32_t)__cvta_generic_to_shared(smh);
    const int BH = 18432;
    float* c0s  = (float*)((char*)smh + 71680);
    float* cufs = c0s + 512;
    float* bls  = cufs + 512;

    int tid = threadIdx.x, wid = tid >> 5, lane = tid & 31;
    int gid = lane >> 2, tig = lane & 3;
    int wr = wid >> 2, wc = wid & 3;
    int colBase = blockIdx.x * 128;
    int hgBase  = blockIdx.x * 32;

    int arow = (lane & 7) + ((lane >> 3) & 1) * 8;
    int ak   = (lane >> 4) * 8;
    int bl   = lane & 15;
    int brow = bl & 7;
    int bk   = ((bl >> 3) & 1) * 8;

#pragma unroll 8
    for (int it = tid; it < 2048; it += 256) {
        int r = it >> 4, q = (it & 15) * 8;
        cp16(sbase + ((BH + r * 136 + q) << 1),
             g_Mleaf + (size_t)(colBase + r) * 128 + q, 16);
    }
    if (tid < 128) {
        cp16((uint32_t)__cvta_generic_to_shared(c0s)  + tid * 16, c0      + tid * 4, 16);
        cp16((uint32_t)__cvta_generic_to_shared(cufs) + tid * 16, g_cuf   + tid * 4, 16);
        cp16((uint32_t)__cvta_generic_to_shared(bls)  + tid * 16, g_bleaf + tid * 4, 16);
    }
    CP_COMMIT();

    auto loadA = [&](int rt, int kc, int st) {
        const __half* src = g_emb16 + (size_t)rt * 128 * 128 + kc * 64;
#pragma unroll
        for (int it = tid; it < 1024; it += 256) {
            int r = it >> 3, q = (it & 7) * 8;
            cp16(sbase + ((st * 9216 + r * 72 + q) << 1), src + (size_t)r * 128 + q, 16);
        }
    };

    loadA(blockIdx.y, 0, 0);
    CP_COMMIT();

    for (int rt = blockIdx.y; rt < 512; rt += 74) {
        loadA(rt, 1, 1);
        CP_COMMIT();

        float acc[4][4][4];
#pragma unroll
        for (int mi = 0; mi < 4; mi++)
#pragma unroll
            for (int ni = 0; ni < 4; ni++)
#pragma unroll
                for (int q = 0; q < 4; q++) acc[mi][ni][q] = 0.f;

#pragma unroll
        for (int kc = 0; kc < 2; kc++) {
            CP_WAIT(1);
            __syncthreads();
#pragma unroll
            for (int ks = 0; ks < 64; ks += 16) {
                uint32_t a[4][4], b[4][2];
#pragma unroll
                for (int mi = 0; mi < 4; mi++)
                    ldm_x4(a[mi], sbase + ((kc * 9216 +
                        (wr * 64 + mi * 16 + arow) * 72 + ks + ak) << 1));
#pragma unroll
                for (int ni = 0; ni < 4; ni++)
                    ldm_x2(b[ni], sbase + ((BH +
                        (wc * 32 + ni * 8 + brow) * 136 + kc * 64 + ks + bk) << 1));
#pragma unroll
                for (int mi = 0; mi < 4; mi++)
#pragma unroll
                    for (int ni = 0; ni < 4; ni++)
                        mma16(acc[mi][ni], a[mi], b[ni]);
            }
            __syncthreads();
            if (kc == 0) {
                int nrt = rt + 74; if (nrt >= 512) nrt = 0;
                loadA(nrt, 0, 0);
                CP_COMMIT();
            }
        }

        float (*Ysq)[36] = (float(*)[36])((char*)smh + 18432);
        int rowBaseG = rt * 128;
        int row = tid >> 1, hq = (tid & 1) * 4;
#pragma unroll
        for (int wq = 0; wq < 4; wq++) {
            if (wc == wq) {
#pragma unroll
                for (int mi = 0; mi < 4; mi++) {
                    int r0 = wr * 64 + mi * 16 + gid;
#pragma unroll
                    for (int ni = 0; ni < 4; ni++) {
                        int col = ni * 8 + tig * 2;
                        float bx = bls[colBase + wq * 32 + col];
                        float by = bls[colBase + wq * 32 + col + 1];
                        Ysq[r0][col]         = acc[mi][ni][0] + bx;
                        Ysq[r0][col + 1]     = acc[mi][ni][1] + by;
                        Ysq[r0 + 8][col]     = acc[mi][ni][2] + bx;
                        Ysq[r0 + 8][col + 1] = acc[mi][ni][3] + by;
                    }
                }
            }
            __syncthreads();
            float hb[4], cb[4];
#pragma unroll
            for (int j = 0; j < 4; j++) {
                int hl = hq + j;
                float4 v = *(const float4*)&Ysq[row][hl * 4];   // i, o, u, wf
                int hg = hgBase + wq * 8 + hl;
                float cc = sigf(v.x) * tanh_fast(v.z);
#pragma unroll
                for (int a = 0; a < 4; a++)
                    cc += sigf(v.w + cufs[a * 128 + hg]) * c0s[a * 128 + hg];
                hb[j] = sigf(v.y) * tanh_fast(cc);
                cb[j] = cc;
            }
            size_t ob = (size_t)(rowBaseG + row) * 128 + hgBase + wq * 8 + hq;
            *(float4*)(out_h + ob) = make_float4(hb[0], hb[1], hb[2], hb[3]);
            *(float4*)(out_c + ob) = make_float4(cb[0], cb[1], cb[2], cb[3]);
            __half2 p0 = __floats2half2_rn(hb[0], hb[1]);
            __half2 p1 = __floats2half2_rn(hb[2], hb[3]);
            uint2 u; u.x = *(const unsigned*)&p0; u.y = *(const unsigned*)&p1;
            *(uint2*)(g_h16 + ob) = u;
            __syncthreads();
        }
    }
}

// ---------------- fused inner: GEMM (128 x 112, K=640) + gates ----------------
// smem halves: A[2][128][72] 0..18432 ; B[2][112][72] 18432..34560 (69.1KB total).
// After mainloop, whole region reused as Ys[128][114] fp32 (58.4KB).
// grid (8, ceil(n/128)). Warp tile: 32 rows x 56 cols (2 m-tiles x 7 n-tiles).
__global__ void __launch_bounds__(256, 2)
fused_inner(int embOff, int hOff, int outOff, const float* __restrict__ cprev,
            float* __restrict__ out_h, float* __restrict__ out_c, int n) {
    extern __shared__ __half smh[];
    uint32_t sbase = (uint32_t)__cvta_generic_to_shared(smh);
    const int BH = 18432;                       // B offset in halves
    const __half* X16  = g_emb16 + (size_t)embOff * 128;
    const __half* Hp16 = g_h16   + (size_t)hOff   * 128;

    int tid = threadIdx.x, wid = tid >> 5, lane = tid & 31;
    int gid = lane >> 2, tig = lane & 3;
    int wr = wid >> 1;            // 0..3, 32-row group
    int wn = wid & 1;             // 0..1, 56-col group
    int rowBase = blockIdx.y * 128, colBase = blockIdx.x * 112;

    int arow = (lane & 7) + ((lane >> 3) & 1) * 8;
    int ak   = (lane >> 4) * 8;
    int bl   = lane & 15;
    int brow = bl & 7;
    int bk   = ((bl >> 3) & 1) * 8;

    float acc[2][7][4];
#pragma unroll
    for (int mi = 0; mi < 2; mi++)
#pragma unroll
        for (int nt = 0; nt < 7; nt++)
#pragma unroll
            for (int q = 0; q < 4; q++) acc[mi][nt][q] = 0.f;

    auto loadAB = [&](int kc, int st) {
        int k0 = kc * 64;
        const __half* base; int pitch, koff;
        if (k0 < 128) { base = X16;  pitch = 128; koff = k0; }
        else          { base = Hp16; pitch = 512; koff = k0 - 128; }
        for (int it = tid; it < 1024; it += 256) {
            int r = it >> 3, q = (it & 7) * 8;
            int row = rowBase + r;
            cp16(sbase + ((st * 9216 + r * 72 + q) << 1),
                 base + (size_t)row * pitch + koff + q, (row < n) ? 16u : 0u);
        }
        for (int it = tid; it < 896; it += 256) {
            int r = it >> 3, q = (it & 7) * 8;
            cp16(sbase + ((BH + st * 8064 + r * 72 + q) << 1),
                 g_Mh + (size_t)(colBase + r) * 640 + k0 + q, 16);
        }
    };

    loadAB(0, 0);
    CP_COMMIT();

    for (int kc = 0; kc < 10; kc++) {
        int cur = kc & 1;
        if (kc < 9) {
            loadAB(kc + 1, cur ^ 1);
            CP_COMMIT();
            CP_WAIT(1);
        } else {
            CP_WAIT(0);
        }
        __syncthreads();
#pragma unroll
        for (int ks = 0; ks < 64; ks += 16) {
            uint32_t a[2][4], b[7][2];
#pragma unroll
            for (int mi = 0; mi < 2; mi++)
                ldm_x4(a[mi], sbase + ((cur * 9216 +
                    (wr * 32 + mi * 16 + arow) * 72 + ks + ak) << 1));
#pragma unroll
            for (int nt = 0; nt < 7; nt++)
                ldm_x2(b[nt], sbase + ((BH + cur * 8064 +
                    (wn * 56 + nt * 8 + brow) * 72 + ks + bk) << 1));
#pragma unroll
            for (int mi = 0; mi < 2; mi++)
#pragma unroll
                for (int nt = 0; nt < 7; nt++)
                    mma16(acc[mi][nt], a[mi], b[nt]);
        }
        __syncthreads();
    }

    // spill full Y tile (+bias) into reused smem, pitch 114 floats
    float (*Ys)[114] = (float(*)[114])smh;
#pragma unroll
    for (int mi = 0; mi < 2; mi++) {
        int r0 = wr * 32 + mi * 16 + gid;
#pragma unroll
        for (int nt = 0; nt < 7; nt++) {
            int col = wn * 56 + nt * 8 + tig * 2;
            float bx = g_bias[colBase + col], by = g_bias[colBase + col + 1];
            *(float2*)&Ys[r0][col]     = make_float2(acc[mi][nt][0] + bx, acc[mi][nt][1] + by);
            *(float2*)&Ys[r0 + 8][col] = make_float2(acc[mi][nt][2] + bx, acc[mi][nt][3] + by);
        }
    }
    __syncthreads();

    // gates: thread -> (row = tid>>1, 8 consecutive H)
    int row = tid >> 1, hhalf = tid & 1;
    int J = rowBase + row;
    if (J < n) {
        int hg0 = blockIdx.x * 16 + hhalf * 8;
        float4 cpv[4][2];
#pragma unroll
        for (int a = 0; a < 4; a++) {
            const float* cp = cprev + (size_t)(4 * J + a) * 128 + hg0;
            cpv[a][0] = *(const float4*)cp;
            cpv[a][1] = *(const float4*)(cp + 4);
        }
        float hb[8], cb[8];
#pragma unroll
        for (int j = 0; j < 8; j++) {
            const float* g = &Ys[row][(hhalf * 8 + j) * 7];
            float cc = sigf(g[0]) * tanh_fast(g[2]);
#pragma unroll
            for (int a = 0; a < 4; a++)
                cc += sigf(g[3 + a]) * ((const float*)&cpv[a][j >> 2])[j & 3];
            hb[j] = sigf(g[1]) * tanh_fast(cc);
            cb[j] = cc;
        }
        size_t ob = (size_t)(outOff + J) * 128 + hg0;
        *(float4*)(out_h + ob)     = make_float4(hb[0], hb[1], hb[2], hb[3]);
        *(float4*)(out_h + ob + 4) = make_float4(hb[4], hb[5], hb[6], hb[7]);
        *(float4*)(out_c + ob)     = make_float4(cb[0], cb[1], cb[2], cb[3]);
        *(float4*)(out_c + ob + 4) = make_float4(cb[4], cb[5], cb[6], cb[7]);
        __half2 p0 = __floats2half2_rn(hb[0], hb[1]);
        __half2 p1 = __floats2half2_rn(hb[2], hb[3]);
        __half2 p2 = __floats2half2_rn(hb[4], hb[5]);
        __half2 p3 = __floats2half2_rn(hb[6], hb[7]);
        uint4 u;
        u.x = *(const unsigned*)&p0; u.y = *(const unsigned*)&p1;
        u.z = *(const unsigned*)&p2; u.w = *(const unsigned*)&p3;
        *(uint4*)(g_h16 + ob) = u;
    }
}

// ---------------- launch ----------------
extern "C" void kernel_launch(void* const* d_in, const int* in_sizes, int n_in,
                              void* d_out, int out_size) {
    const float* emb    = (const float*)d_in[0];
    const float* W_iou  = (const float*)d_in[1];
    const float* b_iou  = (const float*)d_in[2];
    const float* U_iou  = (const float*)d_in[3];
    const float* b_uiou = (const float*)d_in[4];
    const float* W_f    = (const float*)d_in[5];
    const float* b_wf   = (const float*)d_in[6];
    const float* U_f    = (const float*)d_in[7];
    const float* b_uf   = (const float*)d_in[8];
    const float* h0     = (const float*)d_in[9];
    const float* c0     = (const float*)d_in[10];

    float* out_h = (float*)d_out;
    float* out_c = out_h + (size_t)NN * 128;

    cudaFuncSetAttribute(leaf_fused,  cudaFuncAttributeMaxDynamicSharedMemorySize, 77824);
    cudaFuncSetAttribute(fused_inner, cudaFuncAttributeMaxDynamicSharedMemorySize, 69120);

    prep_M_kernel<<<512, 256>>>(W_iou, U_iou, b_iou, b_uiou, W_f, U_f, b_wf, b_uf);
    emb2h_kernel<<<512, 256>>>(emb);
    prep_const_kernel<<<112, 256>>>(U_iou, b_iou, b_uiou, U_f, b_uf, h0, b_wf);

    const int lev_n[9] = {65536, 16384, 4096, 1024, 256, 64, 16, 4, 1};
    int offs[10];
    offs[0] = 0;
    for (int i = 0; i < 9; i++) offs[i + 1] = offs[i] + lev_n[i];

    // leaf level: persistent fused kernel (also fills g_h16[0:65536])
    leaf_fused<<<dim3(4, 74), 256, 77824>>>(c0, out_h, out_c);

    // inner levels 7..0: fused GEMM+gates
    for (int i = 1; i < 9; i++) {
        int n = lev_n[i];
        const float* Cp = out_c + (size_t)offs[i - 1] * 128;
        fused_inner<<<dim3(8, (n + 127) / 128), 256, 69120>>>(
            offs[i], offs[i - 1], offs[i], Cp, out_h, out_c, n);
    }
}